// round 2
// baseline (speedup 1.0000x reference)
#include <cuda_runtime.h>
#include <math.h>

#define B   8
#define C   64
#define DW  128
#define IH  256
#define IW  256
#define HW  65536
#define EPS 1e-6f

// ---------- packed fp32x2 helpers (ptxas won't auto-fuse; PTX only) ----------
__device__ __forceinline__ double pack2(float lo, float hi) {
    double r; asm("mov.b64 %0,{%1,%2};" : "=d"(r) : "f"(lo), "f"(hi)); return r;
}
__device__ __forceinline__ void unpack2(double v, float& lo, float& hi) {
    asm("mov.b64 {%0,%1},%2;" : "=f"(lo), "=f"(hi) : "d"(v));
}
__device__ __forceinline__ double fma2(double a, double b, double c) {
    double r; asm("fma.rn.f32x2 %0,%1,%2,%3;" : "=d"(r) : "d"(a), "d"(b), "d"(c)); return r;
}
__device__ __forceinline__ double add2(double a, double b) {
    double r; asm("add.rn.f32x2 %0,%1,%2;" : "=d"(r) : "d"(a), "d"(b)); return r;
}
__device__ __forceinline__ double mul2(double a, double b) {
    double r; asm("mul.rn.f32x2 %0,%1,%2;" : "=d"(r) : "d"(a), "d"(b)); return r;
}

// ---------------- device scratch ----------------------------------------------
__device__ float g_w1[B*DW*C];
__device__ float g_w2[B*DW*9];
__device__ float g_w3[B*C*C];
__device__ float g_w4[B*DW*C];
__device__ float g_w5[B*C*C];
__device__ float g_t1[(size_t)B*DW*HW];
__device__ float g_t2[(size_t)B*C*HW];
__device__ float g_pool[B*C];
__device__ float g_sca[B*C];

// ---------------- prep: frobenius-normalize hyper weights, zero pool ----------
__global__ void k_prep(const float* __restrict__ w1, const float* __restrict__ w2,
                       const float* __restrict__ w3, const float* __restrict__ w4,
                       const float* __restrict__ w5) {
    int blk = blockIdx.x, t = threadIdx.x;
    const float* src; float* dst; int L;
    if (blk < 1024)      { int r = blk;        src = w1 + r*64; dst = g_w1 + r*64; L = 64; }
    else if (blk < 2048) { int r = blk - 1024; src = w2 + r*9;  dst = g_w2 + r*9;  L = 9;  }
    else if (blk < 2560) { int r = blk - 2048; src = w3 + r*64; dst = g_w3 + r*64; L = 64; }
    else if (blk < 3584) { int r = blk - 2560; src = w4 + r*64; dst = g_w4 + r*64; L = 64; }
    else if (blk < 4096) { int r = blk - 3584; src = w5 + r*64; dst = g_w5 + r*64; L = 64; }
    else { for (int i = t; i < B*C; i += 32) g_pool[i] = 0.f; return; }
    float sq = 0.f;
    for (int i = t; i < L; i += 32) { float v = src[i]; sq += v*v; }
    #pragma unroll
    for (int off = 16; off; off >>= 1) sq += __shfl_xor_sync(0xffffffffu, sq, off);
    float rn = 1.0f / sqrtf(sq);
    for (int i = t; i < L; i += 32) dst[i] = src[i] * rn;
}

// ---------------- K1: LN1 + pw1 (64 -> 128), packed f32x2 matvec --------------
__global__ void __launch_bounds__(128) k1(const float* __restrict__ inp,
                                          const float* __restrict__ b1,
                                          const float* __restrict__ ln1w,
                                          const float* __restrict__ ln1b) {
    __shared__ __align__(16) float Ws[DW*C];
    __shared__ float bs[DW];
    __shared__ float lw[C], lb[C];
    int b = blockIdx.y;
    {
        const float4* Wg = (const float4*)(g_w1 + (size_t)b*DW*C);
        float4* Wd = (float4*)Ws;
        for (int i = threadIdx.x; i < DW*C/4; i += 128) Wd[i] = Wg[i];
    }
    if (threadIdx.x < DW) bs[threadIdx.x] = b1[b*DW + threadIdx.x];
    if (threadIdx.x < C)  { lw[threadIdx.x] = ln1w[threadIdx.x]; lb[threadIdx.x] = ln1b[threadIdx.x]; }
    __syncthreads();

    int p = blockIdx.x * 128 + threadIdx.x;
    const float* xin = inp + (size_t)b*C*HW + p;
    float x[C];
    float sum = 0.f, sq = 0.f;
    #pragma unroll
    for (int c = 0; c < C; c++) { float v = xin[(size_t)c*HW]; x[c] = v; sum += v; sq += v*v; }
    float mu  = sum * (1.f/C);
    float var = sq  * (1.f/C) - mu*mu;
    float s   = rsqrtf(var + EPS);

    double xp[C/2];
    #pragma unroll
    for (int c2 = 0; c2 < C/2; c2++) {
        float a = (x[2*c2]   - mu) * s * lw[2*c2]   + lb[2*c2];
        float d = (x[2*c2+1] - mu) * s * lw[2*c2+1] + lb[2*c2+1];
        xp[c2] = pack2(a, d);
    }

    float* out = g_t1 + (size_t)b*DW*HW + p;
    #pragma unroll 2
    for (int o = 0; o < DW; o++) {
        const double2* wr = (const double2*)(Ws + o*C);
        double a0 = 0.0, a1 = 0.0;
        #pragma unroll
        for (int q = 0; q < C/4; q++) {
            double2 w = wr[q];
            a0 = fma2(w.x, xp[2*q],   a0);
            a1 = fma2(w.y, xp[2*q+1], a1);
        }
        float l0,h0,l1,h1; unpack2(a0,l0,h0); unpack2(a1,l1,h1);
        out[(size_t)o*HW] = bs[o] + ((l0+h0)+(l1+h1));
    }
}

// ---------------- K_dw: depthwise 3x3 + SimpleGate + pool partials ------------
__global__ void __launch_bounds__(256) kdw(const float* __restrict__ b2) {
    int bc = blockIdx.z; int b = bc >> 6; int c = bc & 63;
    __shared__ float s1[10][34];
    __shared__ float s2[10][34];
    __shared__ float wA[9], wB[9];
    __shared__ float bAB[2];
    __shared__ float red[8];

    const float* in1 = g_t1 + ((size_t)b*DW + c     ) * HW;
    const float* in2 = g_t1 + ((size_t)b*DW + c + 64) * HW;
    int x0 = blockIdx.x * 32, y0 = blockIdx.y * 8;

    for (int i = threadIdx.x; i < 340; i += 256) {
        int ly = i / 34, lx = i % 34;
        int gy = y0 + ly - 1, gx = x0 + lx - 1;
        bool ok = (gy >= 0 && gy < IH && gx >= 0 && gx < IW);
        s1[ly][lx] = ok ? in1[gy*IW + gx] : 0.f;
        s2[ly][lx] = ok ? in2[gy*IW + gx] : 0.f;
    }
    if (threadIdx.x < 9)        wA[threadIdx.x]      = g_w2[((size_t)b*DW + c     )*9 + threadIdx.x];
    else if (threadIdx.x < 18)  wB[threadIdx.x - 9]  = g_w2[((size_t)b*DW + c + 64)*9 + threadIdx.x - 9];
    else if (threadIdx.x == 18) bAB[0] = b2[b*DW + c];
    else if (threadIdx.x == 19) bAB[1] = b2[b*DW + c + 64];
    __syncthreads();

    int lx = threadIdx.x & 31, ly = threadIdx.x >> 5;
    float a = bAB[0], d = bAB[1];
    #pragma unroll
    for (int ky = 0; ky < 3; ky++)
        #pragma unroll
        for (int kx = 0; kx < 3; kx++) {
            a += wA[ky*3 + kx] * s1[ly + ky][lx + kx];
            d += wB[ky*3 + kx] * s2[ly + ky][lx + kx];
        }
    float g = a * d;
    g_t2[((size_t)b*C + c)*HW + (y0 + ly)*IW + (x0 + lx)] = g;

    float v = g;
    #pragma unroll
    for (int off = 16; off; off >>= 1) v += __shfl_down_sync(0xffffffffu, v, off);
    if (lx == 0) red[ly] = v;
    __syncthreads();
    if (threadIdx.x == 0) {
        float t = 0.f;
        #pragma unroll
        for (int i = 0; i < 8; i++) t += red[i];
        atomicAdd(&g_pool[b*C + c], t);
    }
}

// ---------------- K_sca -------------------------------------------------------
__global__ void ksca(const float* __restrict__ sca_w, const float* __restrict__ sca_b) {
    int b = blockIdx.x, o = threadIdx.x;
    float acc = sca_b[o];
    #pragma unroll 8
    for (int cc = 0; cc < C; cc++)
        acc += sca_w[o*C + cc] * (g_pool[b*C + cc] * (1.f/(float)HW));
    g_sca[b*C + o] = acc;
}

// ---------------- K2: sca*x -> pw3 -> +res -> LN2 -> pw4 -> gate -> pw5 -> out
__global__ void __launch_bounds__(128) k2(const float* __restrict__ inp,
                                          const float* __restrict__ b3,
                                          const float* __restrict__ b4,
                                          const float* __restrict__ b5,
                                          const float* __restrict__ ln2w,
                                          const float* __restrict__ ln2b,
                                          const float* __restrict__ beta,
                                          const float* __restrict__ gamma,
                                          float* __restrict__ out) {
    __shared__ __align__(16) float Wbuf[DW*C];    // reused W3 / W4 / W5
    __shared__ float b3s[C], b4s[DW], b5s[C];
    __shared__ float l2w[C], l2b[C], il2w[C], bet[C], gam[C], scs[C];
    int b = blockIdx.y;

    if (threadIdx.x < C) {
        int t = threadIdx.x;
        b3s[t] = b3[b*C + t];
        b5s[t] = b5[b*C + t];
        float w = ln2w[t];
        l2w[t] = w; l2b[t] = ln2b[t]; il2w[t] = 1.f / w;
        bet[t] = beta[t]; gam[t] = gamma[t];
        scs[t] = g_sca[b*C + t];
    } else {
        int t = threadIdx.x - C;
        b4s[t]     = b4[b*DW + t];
        b4s[t+64]  = b4[b*DW + t + 64];
    }
    {
        const float4* Wg = (const float4*)(g_w3 + (size_t)b*C*C);
        float4* Wd = (float4*)Wbuf;
        for (int i = threadIdx.x; i < C*C/4; i += 128) Wd[i] = Wg[i];
    }
    __syncthreads();

    int p = blockIdx.x * 128 + threadIdx.x;

    // gated tensor * channel attention, packed
    double xp[C/2];
    const float* t2p = g_t2 + (size_t)b*C*HW + p;
    #pragma unroll
    for (int c2 = 0; c2 < C/2; c2++) {
        float a = t2p[(size_t)(2*c2  )*HW] * scs[2*c2];
        float d = t2p[(size_t)(2*c2+1)*HW] * scs[2*c2+1];
        xp[c2] = pack2(a, d);
    }

    // pw3 + residual -> y; LN2 stats on the fly
    float y[C];
    const float* ip = inp + (size_t)b*C*HW + p;
    float sum = 0.f, sq = 0.f;
    #pragma unroll 2
    for (int o = 0; o < C; o++) {
        const double2* wr = (const double2*)(Wbuf + o*C);
        double a0 = 0.0, a1 = 0.0;
        #pragma unroll
        for (int q = 0; q < C/4; q++) {
            double2 w = wr[q];
            a0 = fma2(w.x, xp[2*q],   a0);
            a1 = fma2(w.y, xp[2*q+1], a1);
        }
        float l0,h0,l1,h1; unpack2(a0,l0,h0); unpack2(a1,l1,h1);
        float acc = b3s[o] + ((l0+h0)+(l1+h1));
        float yv = ip[(size_t)o*HW] + acc * bet[o];
        y[o] = yv; sum += yv; sq += yv*yv;
    }
    float mu  = sum * (1.f/C);
    float var = sq  * (1.f/C) - mu*mu;
    float s   = rsqrtf(var + EPS);
    float is  = sqrtf(var + EPS);

    // normalized y, packed in channel pairs
    double yp[C/2];
    #pragma unroll
    for (int o2 = 0; o2 < C/2; o2++) {
        float a = (y[2*o2]   - mu) * s * l2w[2*o2]   + l2b[2*o2];
        float d = (y[2*o2+1] - mu) * s * l2w[2*o2+1] + l2b[2*o2+1];
        yp[o2] = pack2(a, d);
    }

    __syncthreads();
    {
        const float4* Wg = (const float4*)(g_w4 + (size_t)b*DW*C);
        float4* Wd = (float4*)Wbuf;
        for (int i = threadIdx.x; i < DW*C/4; i += 128) Wd[i] = Wg[i];
    }
    __syncthreads();

    // pw4 + SimpleGate -> gt (packed pairs)
    double gtp[C/2];
    #pragma unroll 1
    for (int j = 0; j < C; j += 2) {
        float gg[2];
        #pragma unroll
        for (int u = 0; u < 2; u++) {
            int c2 = j + u;
            const double2* w1r = (const double2*)(Wbuf + c2*C);
            const double2* w2r = (const double2*)(Wbuf + (c2+64)*C);
            double a0 = 0.0, a1 = 0.0, d0 = 0.0, d1 = 0.0;
            #pragma unroll
            for (int q = 0; q < C/4; q++) {
                double2 wa = w1r[q];
                double2 wb = w2r[q];
                a0 = fma2(wa.x, yp[2*q],   a0);
                a1 = fma2(wa.y, yp[2*q+1], a1);
                d0 = fma2(wb.x, yp[2*q],   d0);
                d1 = fma2(wb.y, yp[2*q+1], d1);
            }
            float l0,h0,l1,h1; unpack2(a0,l0,h0); unpack2(a1,l1,h1);
            float m0,n0,m1,n1; unpack2(d0,m0,n0); unpack2(d1,m1,n1);
            float va = b4s[c2]      + ((l0+h0)+(l1+h1));
            float vb = b4s[c2 + 64] + ((m0+n0)+(m1+n1));
            gg[u] = va * vb;
        }
        gtp[j/2] = pack2(gg[0], gg[1]);
    }

    __syncthreads();
    {
        const float4* Wg = (const float4*)(g_w5 + (size_t)b*C*C);
        float4* Wd = (float4*)Wbuf;
        for (int i = threadIdx.x; i < C*C/4; i += 128) Wd[i] = Wg[i];
    }
    __syncthreads();

    // pw5 + un-normalize y + final residual
    float* op = out + (size_t)b*C*HW + p;
    #pragma unroll 2
    for (int o = 0; o < C; o++) {
        const double2* wr = (const double2*)(Wbuf + o*C);
        double a0 = 0.0, a1 = 0.0;
        #pragma unroll
        for (int q = 0; q < C/4; q++) {
            double2 w = wr[q];
            a0 = fma2(w.x, gtp[2*q],   a0);
            a1 = fma2(w.y, gtp[2*q+1], a1);
        }
        float l0,h0,l1,h1; unpack2(a0,l0,h0); unpack2(a1,l1,h1);
        float acc = b5s[o] + ((l0+h0)+(l1+h1));
        float ylo, yhi; unpack2(yp[o/2], ylo, yhi);
        float yn = (o & 1) ? yhi : ylo;
        float yo = (yn - l2b[o]) * il2w[o] * is + mu;
        op[(size_t)o*HW] = yo + acc * gam[o];
    }
}

// ---------------- launch ------------------------------------------------------
extern "C" void kernel_launch(void* const* d_in, const int* in_sizes, int n_in,
                              void* d_out, int out_size) {
    const float* inp   = (const float*)d_in[0];
    const float* w1    = (const float*)d_in[1];
    const float* b1    = (const float*)d_in[2];
    const float* w2    = (const float*)d_in[3];
    const float* b2    = (const float*)d_in[4];
    const float* w3    = (const float*)d_in[5];
    const float* b3    = (const float*)d_in[6];
    const float* w4    = (const float*)d_in[7];
    const float* b4    = (const float*)d_in[8];
    const float* w5    = (const float*)d_in[9];
    const float* b5    = (const float*)d_in[10];
    const float* ln1w  = (const float*)d_in[11];
    const float* ln1b  = (const float*)d_in[12];
    const float* ln2w  = (const float*)d_in[13];
    const float* ln2b  = (const float*)d_in[14];
    const float* scaw  = (const float*)d_in[15];
    const float* scab  = (const float*)d_in[16];
    const float* beta  = (const float*)d_in[17];
    const float* gamma = (const float*)d_in[18];
    float* out = (float*)d_out;

    k_prep<<<4097, 32>>>(w1, w2, w3, w4, w5);
    k1<<<dim3(HW/128, B), 128>>>(inp, b1, ln1w, ln1b);
    kdw<<<dim3(IW/32, IH/8, B*C), 256>>>(b2);
    ksca<<<B, C>>>(scaw, scab);
    k2<<<dim3(HW/128, B), 128>>>(inp, b3, b4, b5, ln2w, ln2b, beta, gamma, out);
}

// round 3
// speedup vs baseline: 1.0711x; 1.0711x over previous
#include <cuda_runtime.h>
#include <math.h>

#define B   8
#define C   64
#define DW  128
#define IH  256
#define IW  256
#define HW  65536
#define EPS 1e-6f

// ---------- packed fp32x2 helpers ----------
__device__ __forceinline__ double pack2(float lo, float hi) {
    double r; asm("mov.b64 %0,{%1,%2};" : "=d"(r) : "f"(lo), "f"(hi)); return r;
}
__device__ __forceinline__ void unpack2(double v, float& lo, float& hi) {
    asm("mov.b64 {%0,%1},%2;" : "=f"(lo), "=f"(hi) : "d"(v));
}
__device__ __forceinline__ double fma2(double a, double b, double c) {
    double r; asm("fma.rn.f32x2 %0,%1,%2,%3;" : "=d"(r) : "d"(a), "d"(b), "d"(c)); return r;
}
__device__ __forceinline__ float hadd2(double a, double b) {
    float l0,h0,l1,h1; unpack2(a,l0,h0); unpack2(b,l1,h1);
    return (l0+h0)+(l1+h1);
}

// ---------------- device scratch ----------------------------------------------
__device__ float g_w1[B*DW*C];
__device__ float g_w2[B*DW*9];
__device__ float g_w3[B*C*C];
__device__ float g_w4[B*DW*C];
__device__ float g_w5[B*C*C];
__device__ float g_t1[(size_t)B*DW*HW];   // pw1 output; later reused as y buffer
__device__ float g_t2[(size_t)B*C*HW];    // gated tensor
__device__ float g_pool[B*C];

// ---------------- prep --------------------------------------------------------
__global__ void k_prep(const float* __restrict__ w1, const float* __restrict__ w2,
                       const float* __restrict__ w3, const float* __restrict__ w4,
                       const float* __restrict__ w5) {
    int blk = blockIdx.x, t = threadIdx.x;
    const float* src; float* dst; int L;
    if (blk < 1024)      { int r = blk;        src = w1 + r*64; dst = g_w1 + r*64; L = 64; }
    else if (blk < 2048) { int r = blk - 1024; src = w2 + r*9;  dst = g_w2 + r*9;  L = 9;  }
    else if (blk < 2560) { int r = blk - 2048; src = w3 + r*64; dst = g_w3 + r*64; L = 64; }
    else if (blk < 3584) { int r = blk - 2560; src = w4 + r*64; dst = g_w4 + r*64; L = 64; }
    else if (blk < 4096) { int r = blk - 3584; src = w5 + r*64; dst = g_w5 + r*64; L = 64; }
    else { for (int i = t; i < B*C; i += 32) g_pool[i] = 0.f; return; }
    float sq = 0.f;
    for (int i = t; i < L; i += 32) { float v = src[i]; sq += v*v; }
    #pragma unroll
    for (int off = 16; off; off >>= 1) sq += __shfl_xor_sync(0xffffffffu, sq, off);
    float rn = 1.0f / sqrtf(sq);
    for (int i = t; i < L; i += 32) dst[i] = src[i] * rn;
}

// ---------------- K1: LN1 + pw1 (64->128), 2 pixels/thread, f32x2 -------------
__global__ void __launch_bounds__(128) k1(const float* __restrict__ inp,
                                          const float* __restrict__ b1,
                                          const float* __restrict__ ln1w,
                                          const float* __restrict__ ln1b) {
    __shared__ __align__(16) float Ws[DW*C];
    __shared__ float bs[DW];
    __shared__ float lw[C], lb[C];
    int b = blockIdx.y;
    {
        const float4* Wg = (const float4*)(g_w1 + (size_t)b*DW*C);
        float4* Wd = (float4*)Ws;
        for (int i = threadIdx.x; i < DW*C/4; i += 128) Wd[i] = Wg[i];
    }
    if (threadIdx.x < DW) bs[threadIdx.x] = b1[b*DW + threadIdx.x];
    if (threadIdx.x < C)  { lw[threadIdx.x] = ln1w[threadIdx.x]; lb[threadIdx.x] = ln1b[threadIdx.x]; }
    __syncthreads();

    int p0 = (blockIdx.x * 128 + threadIdx.x) * 2;
    const float* xin = inp + (size_t)b*C*HW + p0;

    float xa[C], xb[C];
    float sa = 0.f, qa = 0.f, sb = 0.f, qb = 0.f;
    #pragma unroll
    for (int c = 0; c < C; c++) {
        float2 v = *(const float2*)(xin + (size_t)c*HW);
        xa[c] = v.x; xb[c] = v.y;
        sa += v.x; qa += v.x*v.x;
        sb += v.y; qb += v.y*v.y;
    }
    float mua = sa*(1.f/C), mub = sb*(1.f/C);
    float ra = rsqrtf(qa*(1.f/C) - mua*mua + EPS);
    float rb = rsqrtf(qb*(1.f/C) - mub*mub + EPS);

    double xpa[C/2], xpb[C/2];
    #pragma unroll
    for (int c2 = 0; c2 < C/2; c2++) {
        int c = 2*c2;
        xpa[c2] = pack2((xa[c]-mua)*ra*lw[c]+lb[c], (xa[c+1]-mua)*ra*lw[c+1]+lb[c+1]);
        xpb[c2] = pack2((xb[c]-mub)*rb*lw[c]+lb[c], (xb[c+1]-mub)*rb*lw[c+1]+lb[c+1]);
    }

    float* out = g_t1 + (size_t)b*DW*HW + p0;
    #pragma unroll 2
    for (int o = 0; o < DW; o++) {
        const double2* wr = (const double2*)(Ws + o*C);
        double a0=0.0, a1=0.0, c0=0.0, c1=0.0;
        #pragma unroll
        for (int q = 0; q < C/4; q++) {
            double2 w = wr[q];
            a0 = fma2(w.x, xpa[2*q],   a0);
            a1 = fma2(w.y, xpa[2*q+1], a1);
            c0 = fma2(w.x, xpb[2*q],   c0);
            c1 = fma2(w.y, xpb[2*q+1], c1);
        }
        float2 r; r.x = bs[o] + hadd2(a0,a1); r.y = bs[o] + hadd2(c0,c1);
        *(float2*)(out + (size_t)o*HW) = r;
    }
}

// ---------------- K_dw: depthwise 3x3 + SimpleGate + pool ---------------------
__global__ void __launch_bounds__(256) kdw(const float* __restrict__ b2) {
    int bc = blockIdx.z; int b = bc >> 6; int c = bc & 63;
    __shared__ float s1[10][34];
    __shared__ float s2[10][34];
    __shared__ float wA[9], wB[9];
    __shared__ float bAB[2];
    __shared__ float red[8];

    const float* in1 = g_t1 + ((size_t)b*DW + c     ) * HW;
    const float* in2 = g_t1 + ((size_t)b*DW + c + 64) * HW;
    int x0 = blockIdx.x * 32, y0 = blockIdx.y * 8;

    for (int i = threadIdx.x; i < 340; i += 256) {
        int ly = i / 34, lx = i % 34;
        int gy = y0 + ly - 1, gx = x0 + lx - 1;
        bool ok = (gy >= 0 && gy < IH && gx >= 0 && gx < IW);
        s1[ly][lx] = ok ? in1[gy*IW + gx] : 0.f;
        s2[ly][lx] = ok ? in2[gy*IW + gx] : 0.f;
    }
    if (threadIdx.x < 9)        wA[threadIdx.x]      = g_w2[((size_t)b*DW + c     )*9 + threadIdx.x];
    else if (threadIdx.x < 18)  wB[threadIdx.x - 9]  = g_w2[((size_t)b*DW + c + 64)*9 + threadIdx.x - 9];
    else if (threadIdx.x == 18) bAB[0] = b2[b*DW + c];
    else if (threadIdx.x == 19) bAB[1] = b2[b*DW + c + 64];
    __syncthreads();

    int lx = threadIdx.x & 31, ly = threadIdx.x >> 5;
    float a = bAB[0], d = bAB[1];
    #pragma unroll
    for (int ky = 0; ky < 3; ky++)
        #pragma unroll
        for (int kx = 0; kx < 3; kx++) {
            a += wA[ky*3 + kx] * s1[ly + ky][lx + kx];
            d += wB[ky*3 + kx] * s2[ly + ky][lx + kx];
        }
    float g = a * d;
    g_t2[((size_t)b*C + c)*HW + (y0 + ly)*IW + (x0 + lx)] = g;

    float v = g;
    #pragma unroll
    for (int off = 16; off; off >>= 1) v += __shfl_down_sync(0xffffffffu, v, off);
    if (lx == 0) red[ly] = v;
    __syncthreads();
    if (threadIdx.x == 0) {
        float t = 0.f;
        #pragma unroll
        for (int i = 0; i < 8; i++) t += red[i];
        atomicAdd(&g_pool[b*C + c], t);
    }
}

// ---------------- K2a: sca (in-block) -> sca*x -> pw3 -> +inp*beta -> y -------
__global__ void __launch_bounds__(128) k2a(const float* __restrict__ inp,
                                           const float* __restrict__ b3,
                                           const float* __restrict__ beta,
                                           const float* __restrict__ sca_w,
                                           const float* __restrict__ sca_b) {
    __shared__ __align__(16) float Ws[C*C];
    __shared__ float b3s[C], bet[C], scs[C], pls[C];
    int b = blockIdx.y;
    {
        const float4* Wg = (const float4*)(g_w3 + (size_t)b*C*C);
        float4* Wd = (float4*)Ws;
        for (int i = threadIdx.x; i < C*C/4; i += 128) Wd[i] = Wg[i];
    }
    if (threadIdx.x < C) {
        int t = threadIdx.x;
        b3s[t] = b3[b*C + t];
        bet[t] = beta[t];
        pls[t] = g_pool[b*C + t] * (1.f/(float)HW);
    }
    __syncthreads();
    if (threadIdx.x < C) {
        int o = threadIdx.x;
        float acc = sca_b[o];
        #pragma unroll 8
        for (int cc = 0; cc < C; cc++) acc += sca_w[o*C + cc] * pls[cc];
        scs[o] = acc;
    }
    __syncthreads();

    int p0 = (blockIdx.x * 128 + threadIdx.x) * 2;
    const float* t2p = g_t2 + (size_t)b*C*HW + p0;

    double xpa[C/2], xpb[C/2];
    #pragma unroll
    for (int c2 = 0; c2 < C/2; c2++) {
        int c = 2*c2;
        float2 v0 = *(const float2*)(t2p + (size_t)c*HW);
        float2 v1 = *(const float2*)(t2p + (size_t)(c+1)*HW);
        float s0 = scs[c], s1v = scs[c+1];
        xpa[c2] = pack2(v0.x*s0, v1.x*s1v);
        xpb[c2] = pack2(v0.y*s0, v1.y*s1v);
    }

    const float* ip = inp + (size_t)b*C*HW + p0;
    float* yout = g_t1 + (size_t)b*C*HW + p0;   // reuse t1 as y
    #pragma unroll 2
    for (int o = 0; o < C; o++) {
        const double2* wr = (const double2*)(Ws + o*C);
        double a0=0.0, a1=0.0, c0=0.0, c1=0.0;
        #pragma unroll
        for (int q = 0; q < C/4; q++) {
            double2 w = wr[q];
            a0 = fma2(w.x, xpa[2*q],   a0);
            a1 = fma2(w.y, xpa[2*q+1], a1);
            c0 = fma2(w.x, xpb[2*q],   c0);
            c1 = fma2(w.y, xpb[2*q+1], c1);
        }
        float2 r0 = *(const float2*)(ip + (size_t)o*HW);
        float bo = bet[o], bb = b3s[o];
        float2 r; r.x = r0.x + (bb + hadd2(a0,a1))*bo;
                  r.y = r0.y + (bb + hadd2(c0,c1))*bo;
        *(float2*)(yout + (size_t)o*HW) = r;
    }
}

// ---------------- K2b: LN2 -> pw4 -> gate -> pw5 -> out -----------------------
__global__ void __launch_bounds__(128) k2b(const float* __restrict__ b4,
                                           const float* __restrict__ b5,
                                           const float* __restrict__ ln2w,
                                           const float* __restrict__ ln2b,
                                           const float* __restrict__ gamma,
                                           float* __restrict__ out) {
    __shared__ __align__(16) float Wbuf[DW*C];   // W4 then W5
    __shared__ float b4s[DW], b5s[C];
    __shared__ float l2w[C], l2b[C], il2w[C], gam[C];
    int b = blockIdx.y;

    if (threadIdx.x < C) {
        int t = threadIdx.x;
        b5s[t] = b5[b*C + t];
        float w = ln2w[t];
        l2w[t] = w; l2b[t] = ln2b[t]; il2w[t] = 1.f / w;
        gam[t] = gamma[t];
    } else {
        int t = threadIdx.x - C;
        b4s[t]    = b4[b*DW + t];
        b4s[t+64] = b4[b*DW + t + 64];
    }
    {
        const float4* Wg = (const float4*)(g_w4 + (size_t)b*DW*C);
        float4* Wd = (float4*)Wbuf;
        for (int i = threadIdx.x; i < DW*C/4; i += 128) Wd[i] = Wg[i];
    }
    __syncthreads();

    int p = blockIdx.x * 128 + threadIdx.x;
    const float* yin = g_t1 + (size_t)b*C*HW + p;

    float y[C];
    float sum = 0.f, sq = 0.f;
    #pragma unroll
    for (int c = 0; c < C; c++) {
        float v = yin[(size_t)c*HW];
        y[c] = v; sum += v; sq += v*v;
    }
    float mu  = sum * (1.f/C);
    float var = sq  * (1.f/C) - mu*mu;
    float s   = rsqrtf(var + EPS);
    float is  = sqrtf(var + EPS);

    double yp[C/2];
    #pragma unroll
    for (int o2 = 0; o2 < C/2; o2++) {
        int o = 2*o2;
        yp[o2] = pack2((y[o]-mu)*s*l2w[o]+l2b[o], (y[o+1]-mu)*s*l2w[o+1]+l2b[o+1]);
    }

    // pw4 + SimpleGate
    double gtp[C/2];
    #pragma unroll 1
    for (int j = 0; j < C; j += 2) {
        float gg[2];
        #pragma unroll
        for (int u = 0; u < 2; u++) {
            int c2 = j + u;
            const double2* w1r = (const double2*)(Wbuf + c2*C);
            const double2* w2r = (const double2*)(Wbuf + (c2+64)*C);
            double a0=0.0, a1=0.0, d0=0.0, d1=0.0;
            #pragma unroll
            for (int q = 0; q < C/4; q++) {
                double2 wa = w1r[q];
                double2 wb = w2r[q];
                a0 = fma2(wa.x, yp[2*q],   a0);
                a1 = fma2(wa.y, yp[2*q+1], a1);
                d0 = fma2(wb.x, yp[2*q],   d0);
                d1 = fma2(wb.y, yp[2*q+1], d1);
            }
            float va = b4s[c2]      + hadd2(a0,a1);
            float vb = b4s[c2 + 64] + hadd2(d0,d1);
            gg[u] = va * vb;
        }
        gtp[j/2] = pack2(gg[0], gg[1]);
    }

    __syncthreads();
    {
        const float4* Wg = (const float4*)(g_w5 + (size_t)b*C*C);
        float4* Wd = (float4*)Wbuf;
        for (int i = threadIdx.x; i < C*C/4; i += 128) Wd[i] = Wg[i];
    }
    __syncthreads();

    float* op = out + (size_t)b*C*HW + p;
    #pragma unroll 2
    for (int o = 0; o < C; o++) {
        const double2* wr = (const double2*)(Wbuf + o*C);
        double a0=0.0, a1=0.0;
        #pragma unroll
        for (int q = 0; q < C/4; q++) {
            double2 w = wr[q];
            a0 = fma2(w.x, gtp[2*q],   a0);
            a1 = fma2(w.y, gtp[2*q+1], a1);
        }
        float acc = b5s[o] + hadd2(a0,a1);
        float ylo, yhi; unpack2(yp[o/2], ylo, yhi);
        float yn = (o & 1) ? yhi : ylo;
        float yo = (yn - l2b[o]) * il2w[o] * is + mu;
        op[(size_t)o*HW] = yo + acc * gam[o];
    }
}

// ---------------- launch ------------------------------------------------------
extern "C" void kernel_launch(void* const* d_in, const int* in_sizes, int n_in,
                              void* d_out, int out_size) {
    const float* inp   = (const float*)d_in[0];
    const float* w1    = (const float*)d_in[1];
    const float* b1    = (const float*)d_in[2];
    const float* w2    = (const float*)d_in[3];
    const float* b2    = (const float*)d_in[4];
    const float* w3    = (const float*)d_in[5];
    const float* b3    = (const float*)d_in[6];
    const float* w4    = (const float*)d_in[7];
    const float* b4    = (const float*)d_in[8];
    const float* w5    = (const float*)d_in[9];
    const float* b5    = (const float*)d_in[10];
    const float* ln1w  = (const float*)d_in[11];
    const float* ln1b  = (const float*)d_in[12];
    const float* ln2w  = (const float*)d_in[13];
    const float* ln2b  = (const float*)d_in[14];
    const float* scaw  = (const float*)d_in[15];
    const float* scab  = (const float*)d_in[16];
    const float* beta  = (const float*)d_in[17];
    const float* gamma = (const float*)d_in[18];
    float* out = (float*)d_out;

    k_prep<<<4097, 32>>>(w1, w2, w3, w4, w5);
    k1<<<dim3(HW/256, B), 128>>>(inp, b1, ln1w, ln1b);
    kdw<<<dim3(IW/32, IH/8, B*C), 256>>>(b2);
    k2a<<<dim3(HW/256, B), 128>>>(inp, b3, beta, scaw, scab);
    k2b<<<dim3(HW/128, B), 128>>>(b4, b5, ln2w, ln2b, gamma, out);
}

// round 4
// speedup vs baseline: 1.1818x; 1.1033x over previous
#include <cuda_runtime.h>
#include <math.h>

#define B   8
#define C   64
#define DW  128
#define IH  256
#define IW  256
#define HW  65536
#define EPS 1e-6f
#define XP  132   // smem pixel-row pitch (floats): 16B-aligned rows, conflict-free columns

// ---------- packed fp32x2 helpers ----------
__device__ __forceinline__ double pack2(float lo, float hi) {
    double r; asm("mov.b64 %0,{%1,%2};" : "=d"(r) : "f"(lo), "f"(hi)); return r;
}
__device__ __forceinline__ double fma2(double a, double b, double c) {
    double r; asm("fma.rn.f32x2 %0,%1,%2,%3;" : "=d"(r) : "d"(a), "d"(b), "d"(c)); return r;
}
__device__ __forceinline__ double add2(double a, double b) {
    double r; asm("add.rn.f32x2 %0,%1,%2;" : "=d"(r) : "d"(a), "d"(b)); return r;
}
__device__ __forceinline__ double mul2(double a, double b) {
    double r; asm("mul.rn.f32x2 %0,%1,%2;" : "=d"(r) : "d"(a), "d"(b)); return r;
}

// ---------------- device scratch ----------------------------------------------
__device__ float g_w1t[B*C*DW];   // k-major: [b][c][o]
__device__ float g_w2 [B*DW*9];
__device__ float g_w3t[B*C*C];
__device__ float g_w4t[B*C*DW];
__device__ float g_w5t[B*C*C];
__device__ float g_t1[(size_t)B*DW*HW];   // pw1 out; later y buffer (first B*C*HW)
__device__ float g_t2[(size_t)B*C*HW];
__device__ float g_pool[B*C];

// ---------------- prep: normalize + transpose weights, zero pool --------------
__global__ void k_prep(const float* __restrict__ w1, const float* __restrict__ w2,
                       const float* __restrict__ w3, const float* __restrict__ w4,
                       const float* __restrict__ w5) {
    int blk = blockIdx.x, t = threadIdx.x;
    if (blk >= 4096) { for (int i = t; i < B*C; i += 32) g_pool[i] = 0.f; return; }
    const float* src; float* dstT; int L, stride, lane;
    if (blk < 1024)      { int r = blk;        int b=r>>7, o=r&127; src=w1+r*64; dstT=g_w1t+b*8192+o; stride=128; L=64; lane=o; }
    else if (blk < 2048) { int r = blk - 1024; src=w2+r*9; dstT=g_w2+r*9; stride=1; L=9; lane=0; }
    else if (blk < 2560) { int r = blk - 2048; int b=r>>6, o=r&63;  src=w3+r*64; dstT=g_w3t+b*4096+o; stride=64;  L=64; lane=o; }
    else if (blk < 3584) { int r = blk - 2560; int b=r>>7, o=r&127; src=w4+r*64; dstT=g_w4t+b*8192+o; stride=128; L=64; lane=o; }
    else                 { int r = blk - 3584; int b=r>>6, o=r&63;  src=w5+r*64; dstT=g_w5t+b*4096+o; stride=64;  L=64; lane=o; }
    float sq = 0.f;
    for (int i = t; i < L; i += 32) { float v = src[i]; sq += v*v; }
    #pragma unroll
    for (int off = 16; off; off >>= 1) sq += __shfl_xor_sync(0xffffffffu, sq, off);
    float rn = 1.0f / sqrtf(sq);
    for (int i = t; i < L; i += 32) dstT[(size_t)i*stride] = src[i] * rn;
    (void)lane;
}

// ---------------- K1: LN1 + pw1 GEMM (128 o x 128 px tile) --------------------
// smem: XS[64][XP] @0 (8448f)  WT[64][128] @8448  LW@16640 LB@16704 BS@16768 MU@16896 RS@17024
__global__ void __launch_bounds__(256, 2) k1(const float* __restrict__ inp,
                                             const float* __restrict__ b1,
                                             const float* __restrict__ ln1w,
                                             const float* __restrict__ ln1b) {
    extern __shared__ float sm[];
    float* XS = sm;
    float* WT = sm + 8448;
    float* LW = sm + 16640; float* LB = sm + 16704;
    float* BS = sm + 16768; float* MU = sm + 16896; float* RS = sm + 17024;
    int b = blockIdx.y, px0 = blockIdx.x * 128;
    int tid = threadIdx.x, tx = tid & 15, ty = tid >> 4;

    const float* ibase = inp + (size_t)b*C*HW + px0;
    for (int i = tid; i < 2048; i += 256) {
        int c = i >> 5, p4 = i & 31;
        float4 v = *(const float4*)(ibase + (size_t)c*HW + p4*4);
        *(float4*)(XS + c*XP + p4*4) = v;
    }
    {
        const float4* wg = (const float4*)(g_w1t + (size_t)b*8192);
        float4* wd = (float4*)WT;
        for (int i = tid; i < 2048; i += 256) wd[i] = wg[i];
    }
    if (tid < 128) BS[tid] = b1[b*DW + tid];
    if (tid < 64)  { LW[tid] = ln1w[tid]; LB[tid] = ln1b[tid]; }
    __syncthreads();

    if (tid < 128) {
        float s = 0.f, q = 0.f;
        #pragma unroll
        for (int c = 0; c < 64; c++) { float v = XS[c*XP + tid]; s += v; q += v*v; }
        float mu = s * (1.f/64);
        MU[tid] = mu; RS[tid] = rsqrtf(q*(1.f/64) - mu*mu + EPS);
    }
    __syncthreads();
    for (int i = tid; i < 8192; i += 256) {
        int c = i >> 7, p = i & 127;
        XS[c*XP + p] = (XS[c*XP + p] - MU[p]) * RS[p] * LW[c] + LB[c];
    }
    __syncthreads();

    double acc[8][4];
    #pragma unroll
    for (int u = 0; u < 8; u++) { acc[u][0]=0; acc[u][1]=0; acc[u][2]=0; acc[u][3]=0; }
    int aoff = ty*4;
    #pragma unroll 8
    for (int k = 0; k < 64; k++) {
        const float* wr = WT + k*128;
        float4 wlo = *(const float4*)(wr + aoff);
        float4 whi = *(const float4*)(wr + 64 + aoff);
        double2 xab = *(const double2*)(XS + k*XP + tx*4);
        double2 xcd = *(const double2*)(XS + k*XP + 64 + tx*4);
        double w[8] = { pack2(wlo.x,wlo.x), pack2(wlo.y,wlo.y), pack2(wlo.z,wlo.z), pack2(wlo.w,wlo.w),
                        pack2(whi.x,whi.x), pack2(whi.y,whi.y), pack2(whi.z,whi.z), pack2(whi.w,whi.w) };
        #pragma unroll
        for (int u = 0; u < 8; u++) {
            acc[u][0] = fma2(w[u], xab.x, acc[u][0]);
            acc[u][1] = fma2(w[u], xab.y, acc[u][1]);
            acc[u][2] = fma2(w[u], xcd.x, acc[u][2]);
            acc[u][3] = fma2(w[u], xcd.y, acc[u][3]);
        }
    }

    float* op = g_t1 + (size_t)b*DW*HW + px0;
    #pragma unroll
    for (int u = 0; u < 8; u++) {
        int o = (u < 4) ? (aoff + u) : (64 + aoff + u - 4);
        double bp = pack2(BS[o], BS[o]);
        double2 r0; r0.x = add2(acc[u][0], bp); r0.y = add2(acc[u][1], bp);
        double2 r1; r1.x = add2(acc[u][2], bp); r1.y = add2(acc[u][3], bp);
        *(double2*)(op + (size_t)o*HW + tx*4)      = r0;
        *(double2*)(op + (size_t)o*HW + 64 + tx*4) = r1;
    }
}

// ---------------- K_dw: depthwise 3x3 + SimpleGate + pool ---------------------
__global__ void __launch_bounds__(256) kdw(const float* __restrict__ b2) {
    int bc = blockIdx.z; int b = bc >> 6; int c = bc & 63;
    __shared__ float s1[10][34];
    __shared__ float s2[10][34];
    __shared__ float wA[9], wB[9], bAB[2], red[8];

    const float* in1 = g_t1 + ((size_t)b*DW + c     ) * HW;
    const float* in2 = g_t1 + ((size_t)b*DW + c + 64) * HW;
    int x0 = blockIdx.x * 32, y0 = blockIdx.y * 8;

    for (int i = threadIdx.x; i < 340; i += 256) {
        int ly = i / 34, lx = i % 34;
        int gy = y0 + ly - 1, gx = x0 + lx - 1;
        bool ok = (gy >= 0 && gy < IH && gx >= 0 && gx < IW);
        s1[ly][lx] = ok ? in1[gy*IW + gx] : 0.f;
        s2[ly][lx] = ok ? in2[gy*IW + gx] : 0.f;
    }
    if (threadIdx.x < 9)        wA[threadIdx.x]     = g_w2[((size_t)b*DW + c     )*9 + threadIdx.x];
    else if (threadIdx.x < 18)  wB[threadIdx.x - 9] = g_w2[((size_t)b*DW + c + 64)*9 + threadIdx.x - 9];
    else if (threadIdx.x == 18) bAB[0] = b2[b*DW + c];
    else if (threadIdx.x == 19) bAB[1] = b2[b*DW + c + 64];
    __syncthreads();

    int lx = threadIdx.x & 31, ly = threadIdx.x >> 5;
    float a = bAB[0], d = bAB[1];
    #pragma unroll
    for (int ky = 0; ky < 3; ky++)
        #pragma unroll
        for (int kx = 0; kx < 3; kx++) {
            a += wA[ky*3 + kx] * s1[ly + ky][lx + kx];
            d += wB[ky*3 + kx] * s2[ly + ky][lx + kx];
        }
    float g = a * d;
    g_t2[((size_t)b*C + c)*HW + (y0 + ly)*IW + (x0 + lx)] = g;

    float v = g;
    #pragma unroll
    for (int off = 16; off; off >>= 1) v += __shfl_down_sync(0xffffffffu, v, off);
    if (lx == 0) red[ly] = v;
    __syncthreads();
    if (threadIdx.x == 0) {
        float t = 0.f;
        #pragma unroll
        for (int i = 0; i < 8; i++) t += red[i];
        atomicAdd(&g_pool[b*C + c], t);
    }
}

// ---------------- K2a: sca -> pw3 GEMM -> +inp*beta -> y ----------------------
// smem: XS @0 (8448)  WT(W3t) @8448 (4096)  B3@12544 BET@12608 SCS@12672 PLS@12736
__global__ void __launch_bounds__(256, 2) k2a(const float* __restrict__ inp,
                                              const float* __restrict__ b3,
                                              const float* __restrict__ beta,
                                              const float* __restrict__ sca_w,
                                              const float* __restrict__ sca_b) {
    extern __shared__ float sm[];
    float* XS = sm;
    float* WT = sm + 8448;
    float* B3 = sm + 12544; float* BET = sm + 12608;
    float* SCS = sm + 12672; float* PLS = sm + 12736;
    int b = blockIdx.y, px0 = blockIdx.x * 128;
    int tid = threadIdx.x, tx = tid & 15, ty = tid >> 4;

    const float* t2b = g_t2 + (size_t)b*C*HW + px0;
    for (int i = tid; i < 2048; i += 256) {
        int c = i >> 5, p4 = i & 31;
        float4 v = *(const float4*)(t2b + (size_t)c*HW + p4*4);
        *(float4*)(XS + c*XP + p4*4) = v;
    }
    {
        const float4* wg = (const float4*)(g_w3t + (size_t)b*4096);
        float4* wd = (float4*)WT;
        for (int i = tid; i < 1024; i += 256) wd[i] = wg[i];
    }
    if (tid < 64) {
        B3[tid] = b3[b*C + tid]; BET[tid] = beta[tid];
        PLS[tid] = g_pool[b*C + tid] * (1.f/(float)HW);
    }
    __syncthreads();
    if (tid < 64) {
        float acc = sca_b[tid];
        #pragma unroll 8
        for (int cc = 0; cc < 64; cc++) acc += sca_w[tid*64 + cc] * PLS[cc];
        SCS[tid] = acc;
    }
    __syncthreads();
    for (int i = tid; i < 8192; i += 256) {
        int c = i >> 7, p = i & 127;
        XS[c*XP + p] *= SCS[c];
    }
    __syncthreads();

    double acc[4][4];
    #pragma unroll
    for (int u = 0; u < 4; u++) { acc[u][0]=0; acc[u][1]=0; acc[u][2]=0; acc[u][3]=0; }
    int aoff = ty*4;
    #pragma unroll 8
    for (int k = 0; k < 64; k++) {
        float4 wlo = *(const float4*)(WT + k*64 + aoff);
        double2 xab = *(const double2*)(XS + k*XP + tx*4);
        double2 xcd = *(const double2*)(XS + k*XP + 64 + tx*4);
        double w[4] = { pack2(wlo.x,wlo.x), pack2(wlo.y,wlo.y), pack2(wlo.z,wlo.z), pack2(wlo.w,wlo.w) };
        #pragma unroll
        for (int u = 0; u < 4; u++) {
            acc[u][0] = fma2(w[u], xab.x, acc[u][0]);
            acc[u][1] = fma2(w[u], xab.y, acc[u][1]);
            acc[u][2] = fma2(w[u], xcd.x, acc[u][2]);
            acc[u][3] = fma2(w[u], xcd.y, acc[u][3]);
        }
    }

    const float* ib = inp + (size_t)b*C*HW + px0;
    float* yb = g_t1 + (size_t)b*C*HW + px0;
    #pragma unroll
    for (int u = 0; u < 4; u++) {
        int o = aoff + u;
        double bp  = pack2(B3[o], B3[o]);
        double btp = pack2(BET[o], BET[o]);
        double2 i0 = *(const double2*)(ib + (size_t)o*HW + tx*4);
        double2 i1 = *(const double2*)(ib + (size_t)o*HW + 64 + tx*4);
        double2 r0, r1;
        r0.x = add2(i0.x, mul2(add2(acc[u][0], bp), btp));
        r0.y = add2(i0.y, mul2(add2(acc[u][1], bp), btp));
        r1.x = add2(i1.x, mul2(add2(acc[u][2], bp), btp));
        r1.y = add2(i1.y, mul2(add2(acc[u][3], bp), btp));
        *(double2*)(yb + (size_t)o*HW + tx*4)      = r0;
        *(double2*)(yb + (size_t)o*HW + 64 + tx*4) = r1;
    }
}

// ---------------- K2b: LN2 -> pw4 GEMM -> gate -> pw5 GEMM -> out -------------
// smem: XS @0 (8448)  WT @8448 (8192)  B4@16640(128) B5@16768 L2W@16832 L2B@16896 GAM@16960 MU@17024 RS@17152
__global__ void __launch_bounds__(256, 2) k2b(const float* __restrict__ b4,
                                              const float* __restrict__ b5,
                                              const float* __restrict__ ln2w,
                                              const float* __restrict__ ln2b,
                                              const float* __restrict__ gamma,
                                              float* __restrict__ out) {
    extern __shared__ float sm[];
    float* XS = sm;
    float* WT = sm + 8448;
    float* B4 = sm + 16640; float* B5 = sm + 16768;
    float* L2W = sm + 16832; float* L2B = sm + 16896; float* GAM = sm + 16960;
    float* MU = sm + 17024; float* RS = sm + 17152;
    int b = blockIdx.y, px0 = blockIdx.x * 128;
    int tid = threadIdx.x, tx = tid & 15, ty = tid >> 4;

    const float* ybase = g_t1 + (size_t)b*C*HW + px0;
    for (int i = tid; i < 2048; i += 256) {
        int c = i >> 5, p4 = i & 31;
        float4 v = *(const float4*)(ybase + (size_t)c*HW + p4*4);
        *(float4*)(XS + c*XP + p4*4) = v;
    }
    {
        const float4* wg = (const float4*)(g_w4t + (size_t)b*8192);
        float4* wd = (float4*)WT;
        for (int i = tid; i < 2048; i += 256) wd[i] = wg[i];
    }
    if (tid < 128) B4[tid] = b4[b*DW + tid];
    else {
        int t = tid - 128;
        if (t < 64) { B5[t] = b5[b*C + t]; L2W[t] = ln2w[t]; }
        else if (t < 128) { int u = t - 64; L2B[u] = ln2b[u]; GAM[u] = gamma[u]; }
    }
    __syncthreads();

    if (tid < 128) {
        float s = 0.f, q = 0.f;
        #pragma unroll
        for (int c = 0; c < 64; c++) { float v = XS[c*XP + tid]; s += v; q += v*v; }
        float mu = s * (1.f/64);
        MU[tid] = mu; RS[tid] = rsqrtf(q*(1.f/64) - mu*mu + EPS);
    }
    __syncthreads();
    for (int i = tid; i < 8192; i += 256) {
        int c = i >> 7, p = i & 127;
        XS[c*XP + p] = (XS[c*XP + p] - MU[p]) * RS[p] * L2W[c] + L2B[c];
    }
    __syncthreads();

    // GEMM1: W4 (128 o, rows paired o & o+64 per thread)
    double acc[8][4];
    #pragma unroll
    for (int u = 0; u < 8; u++) { acc[u][0]=0; acc[u][1]=0; acc[u][2]=0; acc[u][3]=0; }
    int aoff = ty*4;
    #pragma unroll 8
    for (int k = 0; k < 64; k++) {
        const float* wr = WT + k*128;
        float4 wlo = *(const float4*)(wr + aoff);
        float4 whi = *(const float4*)(wr + 64 + aoff);
        double2 xab = *(const double2*)(XS + k*XP + tx*4);
        double2 xcd = *(const double2*)(XS + k*XP + 64 + tx*4);
        double w[8] = { pack2(wlo.x,wlo.x), pack2(wlo.y,wlo.y), pack2(wlo.z,wlo.z), pack2(wlo.w,wlo.w),
                        pack2(whi.x,whi.x), pack2(whi.y,whi.y), pack2(whi.z,whi.z), pack2(whi.w,whi.w) };
        #pragma unroll
        for (int u = 0; u < 8; u++) {
            acc[u][0] = fma2(w[u], xab.x, acc[u][0]);
            acc[u][1] = fma2(w[u], xab.y, acc[u][1]);
            acc[u][2] = fma2(w[u], xcd.x, acc[u][2]);
            acc[u][3] = fma2(w[u], xcd.y, acc[u][3]);
        }
    }

    // SimpleGate in registers: pair (o, o+64)
    double gd[4][4];
    #pragma unroll
    for (int u = 0; u < 4; u++) {
        double blo = pack2(B4[aoff+u], B4[aoff+u]);
        double bhi = pack2(B4[64+aoff+u], B4[64+aoff+u]);
        #pragma unroll
        for (int j = 0; j < 4; j++)
            gd[u][j] = mul2(add2(acc[u][j], blo), add2(acc[u+4][j], bhi));
    }
    __syncthreads();   // all GEMM1 smem reads done

    // write gated tile into XS; load W5t
    #pragma unroll
    for (int u = 0; u < 4; u++) {
        double* gr = (double*)(XS + (aoff + u)*XP);
        *(double2*)(gr + tx*2)      = *(double2*)&gd[u][0];
        *(double2*)(gr + 32 + tx*2) = *(double2*)&gd[u][2];
    }
    {
        const float4* wg = (const float4*)(g_w5t + (size_t)b*4096);
        float4* wd = (float4*)WT;
        for (int i = tid; i < 1024; i += 256) wd[i] = wg[i];
    }
    __syncthreads();

    // GEMM2: W5 (64 o)
    double acc2[4][4];
    #pragma unroll
    for (int u = 0; u < 4; u++) { acc2[u][0]=0; acc2[u][1]=0; acc2[u][2]=0; acc2[u][3]=0; }
    #pragma unroll 8
    for (int k = 0; k < 64; k++) {
        float4 wlo = *(const float4*)(WT + k*64 + aoff);
        double2 xab = *(const double2*)(XS + k*XP + tx*4);
        double2 xcd = *(const double2*)(XS + k*XP + 64 + tx*4);
        double w[4] = { pack2(wlo.x,wlo.x), pack2(wlo.y,wlo.y), pack2(wlo.z,wlo.z), pack2(wlo.w,wlo.w) };
        #pragma unroll
        for (int u = 0; u < 4; u++) {
            acc2[u][0] = fma2(w[u], xab.x, acc2[u][0]);
            acc2[u][1] = fma2(w[u], xab.y, acc2[u][1]);
            acc2[u][2] = fma2(w[u], xcd.x, acc2[u][2]);
            acc2[u][3] = fma2(w[u], xcd.y, acc2[u][3]);
        }
    }

    // epilogue: out = y + (acc2 + b5) * gamma   (reload raw y from gmem)
    float* ob = out + (size_t)b*C*HW + px0;
    #pragma unroll
    for (int u = 0; u < 4; u++) {
        int o = aoff + u;
        double bp = pack2(B5[o], B5[o]);
        double gp = pack2(GAM[o], GAM[o]);
        double2 y0 = *(const double2*)(ybase + (size_t)o*HW + tx*4);
        double2 y1 = *(const double2*)(ybase + (size_t)o*HW + 64 + tx*4);
        double2 r0, r1;
        r0.x = add2(y0.x, mul2(add2(acc2[u][0], bp), gp));
        r0.y = add2(y0.y, mul2(add2(acc2[u][1], bp), gp));
        r1.x = add2(y1.x, mul2(add2(acc2[u][2], bp), gp));
        r1.y = add2(y1.y, mul2(add2(acc2[u][3], bp), gp));
        *(double2*)(ob + (size_t)o*HW + tx*4)      = r0;
        *(double2*)(ob + (size_t)o*HW + 64 + tx*4) = r1;
    }
}

// ---------------- launch ------------------------------------------------------
extern "C" void kernel_launch(void* const* d_in, const int* in_sizes, int n_in,
                              void* d_out, int out_size) {
    const float* inp   = (const float*)d_in[0];
    const float* w1    = (const float*)d_in[1];
    const float* b1    = (const float*)d_in[2];
    const float* w2    = (const float*)d_in[3];
    const float* b2    = (const float*)d_in[4];
    const float* w3    = (const float*)d_in[5];
    const float* b3    = (const float*)d_in[6];
    const float* w4    = (const float*)d_in[7];
    const float* b4    = (const float*)d_in[8];
    const float* w5    = (const float*)d_in[9];
    const float* b5    = (const float*)d_in[10];
    const float* ln1w  = (const float*)d_in[11];
    const float* ln1b  = (const float*)d_in[12];
    const float* ln2w  = (const float*)d_in[13];
    const float* ln2b  = (const float*)d_in[14];
    const float* scaw  = (const float*)d_in[15];
    const float* scab  = (const float*)d_in[16];
    const float* beta  = (const float*)d_in[17];
    const float* gamma = (const float*)d_in[18];
    float* out = (float*)d_out;

    // opt into >48KB dynamic smem (host-side attribute; persists across calls)
    cudaFuncSetAttribute(k1,  cudaFuncAttributeMaxDynamicSharedMemorySize, 68608);
    cudaFuncSetAttribute(k2a, cudaFuncAttributeMaxDynamicSharedMemorySize, 51200);
    cudaFuncSetAttribute(k2b, cudaFuncAttributeMaxDynamicSharedMemorySize, 69632);

    k_prep<<<4097, 32>>>(w1, w2, w3, w4, w5);
    k1 <<<dim3(HW/128, B), 256, 68608>>>(inp, b1, ln1w, ln1b);
    kdw<<<dim3(IW/32, IH/8, B*C), 256>>>(b2);
    k2a<<<dim3(HW/128, B), 256, 51200>>>(inp, b3, beta, scaw, scab);
    k2b<<<dim3(HW/128, B), 256, 69632>>>(b4, b5, ln2w, ln2b, gamma, out);
}

// round 5
// speedup vs baseline: 1.3473x; 1.1401x over previous
#include <cuda_runtime.h>
#include <math.h>

#define B   8
#define C   64
#define DW  128
#define IH  256
#define IW  256
#define HW  65536
#define EPS 1e-6f
#define XP  132   // smem pixel-row pitch in floats

// ---------- packed fp32x2 helpers ----------
__device__ __forceinline__ double pack2(float lo, float hi) {
    double r; asm("mov.b64 %0,{%1,%2};" : "=d"(r) : "f"(lo), "f"(hi)); return r;
}
__device__ __forceinline__ double fma2(double a, double b, double c) {
    double r; asm("fma.rn.f32x2 %0,%1,%2,%3;" : "=d"(r) : "d"(a), "d"(b), "d"(c)); return r;
}
__device__ __forceinline__ double add2(double a, double b) {
    double r; asm("add.rn.f32x2 %0,%1,%2;" : "=d"(r) : "d"(a), "d"(b)); return r;
}
__device__ __forceinline__ double mul2(double a, double b) {
    double r; asm("mul.rn.f32x2 %0,%1,%2;" : "=d"(r) : "d"(a), "d"(b)); return r;
}

// ---------------- device scratch ----------------------------------------------
__device__ float g_w1t[B*C*DW];   // k-major, ln1_w-folded: [b][c][o]
__device__ float g_s1 [B*DW];     // row sums of folded w1
__device__ float g_c1 [B*DW];     // sum w1*ln1_b
__device__ float g_w2 [B*DW*9];
__device__ float g_w3t[B*C*C];
__device__ float g_w4t[B*C*DW];   // ln2_w-folded
__device__ float g_s4 [B*DW];
__device__ float g_c4 [B*DW];
__device__ float g_w5t[B*C*C];
__device__ float g_t1[(size_t)B*DW*HW];   // pw1 out; later y buffer
__device__ float g_t2[(size_t)B*C*HW];
__device__ float g_pool[B*C];

// ---------------- prep: normalize, fold LN weights, transpose -----------------
__global__ void k_prep(const float* __restrict__ w1, const float* __restrict__ w2,
                       const float* __restrict__ w3, const float* __restrict__ w4,
                       const float* __restrict__ w5,
                       const float* __restrict__ ln1w, const float* __restrict__ ln1b,
                       const float* __restrict__ ln2w, const float* __restrict__ ln2b) {
    int blk = blockIdx.x, t = threadIdx.x;
    if (blk >= 4096) { for (int i = t; i < B*C; i += 32) g_pool[i] = 0.f; return; }

    if (blk < 1024 || (blk >= 2560 && blk < 3584)) {
        // w1 or w4 rows: fold LN, compute S and C
        bool is1 = (blk < 1024);
        int r = is1 ? blk : blk - 2560;
        const float* src = (is1 ? w1 : w4) + r*64;
        int b = r >> 7, o = r & 127;
        float* dstT = (is1 ? g_w1t : g_w4t) + b*8192 + o;
        const float* lw = is1 ? ln1w : ln2w;
        const float* lb = is1 ? ln1b : ln2b;
        float sq = 0.f;
        for (int i = t; i < 64; i += 32) { float v = src[i]; sq += v*v; }
        #pragma unroll
        for (int off = 16; off; off >>= 1) sq += __shfl_xor_sync(0xffffffffu, sq, off);
        float rn = 1.0f / sqrtf(sq);
        float s = 0.f, cx = 0.f;
        for (int i = t; i < 64; i += 32) {
            float wn = src[i] * rn;
            float wf = wn * lw[i];
            dstT[(size_t)i*128] = wf;
            s += wf; cx += wn * lb[i];
        }
        #pragma unroll
        for (int off = 16; off; off >>= 1) {
            s  += __shfl_xor_sync(0xffffffffu, s,  off);
            cx += __shfl_xor_sync(0xffffffffu, cx, off);
        }
        if (t == 0) {
            if (is1) { g_s1[r] = s; g_c1[r] = cx; }
            else     { g_s4[r] = s; g_c4[r] = cx; }
        }
        return;
    }
    const float* src; float* dstT; int L, stride;
    if (blk < 2048)      { int r = blk - 1024; src=w2+r*9; dstT=g_w2+r*9; stride=1; L=9; }
    else if (blk < 2560) { int r = blk - 2048; int b=r>>6, o=r&63; src=w3+r*64; dstT=g_w3t+b*4096+o; stride=64; L=64; }
    else                 { int r = blk - 3584; int b=r>>6, o=r&63; src=w5+r*64; dstT=g_w5t+b*4096+o; stride=64; L=64; }
    float sq = 0.f;
    for (int i = t; i < L; i += 32) { float v = src[i]; sq += v*v; }
    #pragma unroll
    for (int off = 16; off; off >>= 1) sq += __shfl_xor_sync(0xffffffffu, sq, off);
    float rn = 1.0f / sqrtf(sq);
    for (int i = t; i < L; i += 32) dstT[(size_t)i*stride] = src[i] * rn;
}

// ---------------- K1: LN1(folded) + pw1 GEMM, 512 thr, 2 CTA/SM ---------------
// floats: XS@0(8448) WT@8448(8192) BS@16640(128) SS@16768(128) CC@16896(128) MU@17024(128) RS@17152(128)
__global__ void __launch_bounds__(512, 2) k1(const float* __restrict__ inp,
                                             const float* __restrict__ b1) {
    extern __shared__ float sm[];
    float* XS = sm;          float* WT = sm + 8448;
    float* BS = sm + 16640;  float* SS = sm + 16768; float* CC = sm + 16896;
    float* MU = sm + 17024;  float* RS = sm + 17152;
    int b = blockIdx.y, px0 = blockIdx.x * 128;
    int tid = threadIdx.x, tx = tid & 15, ty = tid >> 4;

    const float* ibase = inp + (size_t)b*C*HW + px0;
    for (int i = tid; i < 2048; i += 512) {
        int c = i >> 5, p4 = i & 31;
        *(float4*)(XS + c*XP + p4*4) = *(const float4*)(ibase + (size_t)c*HW + p4*4);
    }
    {
        const float4* wg = (const float4*)(g_w1t + (size_t)b*8192);
        float4* wd = (float4*)WT;
        for (int i = tid; i < 2048; i += 512) wd[i] = wg[i];
    }
    if (tid < 128) { BS[tid] = b1[b*DW + tid]; SS[tid] = g_s1[b*DW + tid]; CC[tid] = g_c1[b*DW + tid]; }
    __syncthreads();

    if (tid < 128) {
        float s = 0.f, q = 0.f;
        #pragma unroll
        for (int c = 0; c < 64; c++) { float v = XS[c*XP + tid]; s += v; q += v*v; }
        float mu = s * (1.f/64);
        MU[tid] = mu; RS[tid] = rsqrtf(q*(1.f/64) - mu*mu + EPS);
    }
    __syncthreads();

    double acc[4][4];
    #pragma unroll
    for (int u = 0; u < 4; u++) { acc[u][0]=0; acc[u][1]=0; acc[u][2]=0; acc[u][3]=0; }
    int o0 = ty * 4;
    #pragma unroll 4
    for (int k = 0; k < 64; k++) {
        float4 w = *(const float4*)(WT + k*128 + o0);
        double2 xab = *(const double2*)(XS + k*XP + tx*4);
        double2 xcd = *(const double2*)(XS + k*XP + 64 + tx*4);
        double wp[4] = { pack2(w.x,w.x), pack2(w.y,w.y), pack2(w.z,w.z), pack2(w.w,w.w) };
        #pragma unroll
        for (int u = 0; u < 4; u++) {
            acc[u][0] = fma2(wp[u], xab.x, acc[u][0]);
            acc[u][1] = fma2(wp[u], xab.y, acc[u][1]);
            acc[u][2] = fma2(wp[u], xcd.x, acc[u][2]);
            acc[u][3] = fma2(wp[u], xcd.y, acc[u][3]);
        }
    }

    double mu0 = *(const double*)(MU + tx*4), mu1 = *(const double*)(MU + tx*4 + 2);
    double mu2 = *(const double*)(MU + 64 + tx*4), mu3 = *(const double*)(MU + 64 + tx*4 + 2);
    double rs0 = *(const double*)(RS + tx*4), rs1 = *(const double*)(RS + tx*4 + 2);
    double rs2 = *(const double*)(RS + 64 + tx*4), rs3 = *(const double*)(RS + 64 + tx*4 + 2);
    float* op = g_t1 + (size_t)b*DW*HW + px0;
    #pragma unroll
    for (int u = 0; u < 4; u++) {
        int o = o0 + u;
        double nS = pack2(-SS[o], -SS[o]);
        float cbf = CC[o] + BS[o];
        double cb = pack2(cbf, cbf);
        double2 r0, r1;
        r0.x = add2(mul2(fma2(mu0, nS, acc[u][0]), rs0), cb);
        r0.y = add2(mul2(fma2(mu1, nS, acc[u][1]), rs1), cb);
        r1.x = add2(mul2(fma2(mu2, nS, acc[u][2]), rs2), cb);
        r1.y = add2(mul2(fma2(mu3, nS, acc[u][3]), rs3), cb);
        *(double2*)(op + (size_t)o*HW + tx*4)      = r0;
        *(double2*)(op + (size_t)o*HW + 64 + tx*4) = r1;
    }
}

// ---------------- K_dw: depthwise 3x3 + SimpleGate + pool, 32x32 tiles --------
__global__ void __launch_bounds__(256) kdw(const float* __restrict__ b2) {
    int bc = blockIdx.z; int b = bc >> 6; int c = bc & 63;
    __shared__ float s1[34][36];
    __shared__ float s2[34][36];
    __shared__ float wA[9], wB[9], bAB[2], red[8];

    const float* in1 = g_t1 + ((size_t)b*DW + c     ) * HW;
    const float* in2 = g_t1 + ((size_t)b*DW + c + 64) * HW;
    int x0 = blockIdx.x * 32, y0 = blockIdx.y * 32;

    for (int i = threadIdx.x; i < 34*34; i += 256) {
        int ly = i / 34, lx = i % 34;
        int gy = y0 + ly - 1, gx = x0 + lx - 1;
        bool ok = (gy >= 0 && gy < IH && gx >= 0 && gx < IW);
        s1[ly][lx] = ok ? in1[gy*IW + gx] : 0.f;
        s2[ly][lx] = ok ? in2[gy*IW + gx] : 0.f;
    }
    if (threadIdx.x < 9)        wA[threadIdx.x]     = g_w2[((size_t)b*DW + c     )*9 + threadIdx.x];
    else if (threadIdx.x < 18)  wB[threadIdx.x - 9] = g_w2[((size_t)b*DW + c + 64)*9 + threadIdx.x - 9];
    else if (threadIdx.x == 18) bAB[0] = b2[b*DW + c];
    else if (threadIdx.x == 19) bAB[1] = b2[b*DW + c + 64];
    __syncthreads();

    int lx = threadIdx.x & 31, ly0 = (threadIdx.x >> 5) * 4;
    float* obase = g_t2 + ((size_t)b*C + c)*HW;
    float psum = 0.f;
    #pragma unroll
    for (int r = 0; r < 4; r++) {
        int ly = ly0 + r;
        float a = bAB[0], d = bAB[1];
        #pragma unroll
        for (int ky = 0; ky < 3; ky++)
            #pragma unroll
            for (int kx = 0; kx < 3; kx++) {
                a += wA[ky*3 + kx] * s1[ly + ky][lx + kx];
                d += wB[ky*3 + kx] * s2[ly + ky][lx + kx];
            }
        float g = a * d;
        obase[(y0 + ly)*IW + (x0 + lx)] = g;
        psum += g;
    }
    #pragma unroll
    for (int off = 16; off; off >>= 1) psum += __shfl_down_sync(0xffffffffu, psum, off);
    if (lx == 0) red[threadIdx.x >> 5] = psum;
    __syncthreads();
    if (threadIdx.x == 0) {
        float t = 0.f;
        #pragma unroll
        for (int i = 0; i < 8; i++) t += red[i];
        atomicAdd(&g_pool[b*C + c], t);
    }
}

// ---------------- K2a: sca folded into W3 -> pw3 GEMM -> +inp*beta -> y -------
// floats: XS@0(8448) WT@8448(4096) B3@12544 BET@12608 SCS@12672 PLS@12736
__global__ void __launch_bounds__(256, 3) k2a(const float* __restrict__ inp,
                                              const float* __restrict__ b3,
                                              const float* __restrict__ beta,
                                              const float* __restrict__ sca_w,
                                              const float* __restrict__ sca_b) {
    extern __shared__ float sm[];
    float* XS = sm;          float* WT = sm + 8448;
    float* B3 = sm + 12544;  float* BET = sm + 12608;
    float* SCS = sm + 12672; float* PLS = sm + 12736;
    int b = blockIdx.y, px0 = blockIdx.x * 128;
    int tid = threadIdx.x, tx = tid & 15, ty = tid >> 4;

    const float* t2b = g_t2 + (size_t)b*C*HW + px0;
    for (int i = tid; i < 2048; i += 256) {
        int c = i >> 5, p4 = i & 31;
        *(float4*)(XS + c*XP + p4*4) = *(const float4*)(t2b + (size_t)c*HW + p4*4);
    }
    {
        const float4* wg = (const float4*)(g_w3t + (size_t)b*4096);
        float4* wd = (float4*)WT;
        for (int i = tid; i < 1024; i += 256) wd[i] = wg[i];
    }
    if (tid < 64) {
        B3[tid] = b3[b*C + tid]; BET[tid] = beta[tid];
        PLS[tid] = g_pool[b*C + tid] * (1.f/(float)HW);
    }
    __syncthreads();
    if (tid < 64) {
        float acc = sca_b[tid];
        #pragma unroll 8
        for (int cc = 0; cc < 64; cc++) acc += sca_w[tid*64 + cc] * PLS[cc];
        SCS[tid] = acc;
    }
    __syncthreads();
    // fold sca into weight tile rows (k index)
    for (int i = tid; i < 4096; i += 256) WT[i] *= SCS[i >> 6];
    __syncthreads();

    double acc[4][4];
    #pragma unroll
    for (int u = 0; u < 4; u++) { acc[u][0]=0; acc[u][1]=0; acc[u][2]=0; acc[u][3]=0; }
    int o0 = ty * 4;
    #pragma unroll 4
    for (int k = 0; k < 64; k++) {
        float4 w = *(const float4*)(WT + k*64 + o0);
        double2 xab = *(const double2*)(XS + k*XP + tx*4);
        double2 xcd = *(const double2*)(XS + k*XP + 64 + tx*4);
        double wp[4] = { pack2(w.x,w.x), pack2(w.y,w.y), pack2(w.z,w.z), pack2(w.w,w.w) };
        #pragma unroll
        for (int u = 0; u < 4; u++) {
            acc[u][0] = fma2(wp[u], xab.x, acc[u][0]);
            acc[u][1] = fma2(wp[u], xab.y, acc[u][1]);
            acc[u][2] = fma2(wp[u], xcd.x, acc[u][2]);
            acc[u][3] = fma2(wp[u], xcd.y, acc[u][3]);
        }
    }

    const float* ib = inp + (size_t)b*C*HW + px0;
    float* yb = g_t1 + (size_t)b*C*HW + px0;
    #pragma unroll
    for (int u = 0; u < 4; u++) {
        int o = o0 + u;
        double bp  = pack2(B3[o], B3[o]);
        double btp = pack2(BET[o], BET[o]);
        double2 i0 = *(const double2*)(ib + (size_t)o*HW + tx*4);
        double2 i1 = *(const double2*)(ib + (size_t)o*HW + 64 + tx*4);
        double2 r0, r1;
        r0.x = add2(i0.x, mul2(add2(acc[u][0], bp), btp));
        r0.y = add2(i0.y, mul2(add2(acc[u][1], bp), btp));
        r1.x = add2(i1.x, mul2(add2(acc[u][2], bp), btp));
        r1.y = add2(i1.y, mul2(add2(acc[u][3], bp), btp));
        *(double2*)(yb + (size_t)o*HW + tx*4)      = r0;
        *(double2*)(yb + (size_t)o*HW + 64 + tx*4) = r1;
    }
}

// ---------------- K2b: LN2(folded) -> pw4 -> gate -> pw5 -> out, 512 thr ------
// floats: XS@0(8448) WT@8448(8192) B4@16640(128) S4@16768(128) C4@16896(128)
//         B5@17024(64) GAM@17088(64) MU@17152(128) RS@17280(128)  total 17408
__global__ void __launch_bounds__(512, 2) k2b(const float* __restrict__ b4,
                                              const float* __restrict__ b5,
                                              const float* __restrict__ gamma,
                                              float* __restrict__ out) {
    extern __shared__ float sm[];
    float* XS = sm;          float* WT = sm + 8448;
    float* B4 = sm + 16640;  float* S4 = sm + 16768; float* C4 = sm + 16896;
    float* B5 = sm + 17024;  float* GAM = sm + 17088;
    float* MU = sm + 17152;  float* RS = sm + 17280;
    int b = blockIdx.y, px0 = blockIdx.x * 128;
    int tid = threadIdx.x, tx = tid & 15, ty = tid >> 4;

    const float* ybase = g_t1 + (size_t)b*C*HW + px0;
    for (int i = tid; i < 2048; i += 512) {
        int c = i >> 5, p4 = i & 31;
        *(float4*)(XS + c*XP + p4*4) = *(const float4*)(ybase + (size_t)c*HW + p4*4);
    }
    {
        const float4* wg = (const float4*)(g_w4t + (size_t)b*8192);
        float4* wd = (float4*)WT;
        for (int i = tid; i < 2048; i += 512) wd[i] = wg[i];
    }
    if (tid < 128) { B4[tid] = b4[b*DW + tid]; S4[tid] = g_s4[b*DW + tid]; C4[tid] = g_c4[b*DW + tid]; }
    else if (tid < 192) { int u = tid - 128; B5[u] = b5[b*C + u]; GAM[u] = gamma[u]; }
    __syncthreads();

    if (tid < 128) {
        float s = 0.f, q = 0.f;
        #pragma unroll
        for (int c = 0; c < 64; c++) { float v = XS[c*XP + tid]; s += v; q += v*v; }
        float mu = s * (1.f/64);
        MU[tid] = mu; RS[tid] = rsqrtf(q*(1.f/64) - mu*mu + EPS);
    }
    __syncthreads();

    // GEMM1 on raw y: rows {2ty, 2ty+1, 2ty+64, 2ty+65}
    double acc[4][4];
    #pragma unroll
    for (int u = 0; u < 4; u++) { acc[u][0]=0; acc[u][1]=0; acc[u][2]=0; acc[u][3]=0; }
    int oa0 = 2*ty;
    #pragma unroll 4
    for (int k = 0; k < 64; k++) {
        float2 wlo = *(const float2*)(WT + k*128 + oa0);
        float2 whi = *(const float2*)(WT + k*128 + 64 + oa0);
        double2 xab = *(const double2*)(XS + k*XP + tx*4);
        double2 xcd = *(const double2*)(XS + k*XP + 64 + tx*4);
        double wp[4] = { pack2(wlo.x,wlo.x), pack2(wlo.y,wlo.y), pack2(whi.x,whi.x), pack2(whi.y,whi.y) };
        #pragma unroll
        for (int u = 0; u < 4; u++) {
            acc[u][0] = fma2(wp[u], xab.x, acc[u][0]);
            acc[u][1] = fma2(wp[u], xab.y, acc[u][1]);
            acc[u][2] = fma2(wp[u], xcd.x, acc[u][2]);
            acc[u][3] = fma2(wp[u], xcd.y, acc[u][3]);
        }
    }

    double mu0 = *(const double*)(MU + tx*4), mu1 = *(const double*)(MU + tx*4 + 2);
    double mu2 = *(const double*)(MU + 64 + tx*4), mu3 = *(const double*)(MU + 64 + tx*4 + 2);
    double rs0 = *(const double*)(RS + tx*4), rs1 = *(const double*)(RS + tx*4 + 2);
    double rs2 = *(const double*)(RS + 64 + tx*4), rs3 = *(const double*)(RS + 64 + tx*4 + 2);

    // gate: channels oa0, oa0+1
    double gd[2][4];
    #pragma unroll
    for (int j = 0; j < 2; j++) {
        int oa = oa0 + j, ob = oa + 64;
        double nSa = pack2(-S4[oa], -S4[oa]);
        double nSb = pack2(-S4[ob], -S4[ob]);
        float cbaf = C4[oa] + B4[oa], cbbf = C4[ob] + B4[ob];
        double cba = pack2(cbaf, cbaf), cbb = pack2(cbbf, cbbf);
        double va0 = add2(mul2(fma2(mu0, nSa, acc[j][0]), rs0), cba);
        double va1 = add2(mul2(fma2(mu1, nSa, acc[j][1]), rs1), cba);
        double va2 = add2(mul2(fma2(mu2, nSa, acc[j][2]), rs2), cba);
        double va3 = add2(mul2(fma2(mu3, nSa, acc[j][3]), rs3), cba);
        double vb0 = add2(mul2(fma2(mu0, nSb, acc[j+2][0]), rs0), cbb);
        double vb1 = add2(mul2(fma2(mu1, nSb, acc[j+2][1]), rs1), cbb);
        double vb2 = add2(mul2(fma2(mu2, nSb, acc[j+2][2]), rs2), cbb);
        double vb3 = add2(mul2(fma2(mu3, nSb, acc[j+2][3]), rs3), cbb);
        gd[j][0] = mul2(va0, vb0); gd[j][1] = mul2(va1, vb1);
        gd[j][2] = mul2(va2, vb2); gd[j][3] = mul2(va3, vb3);
    }
    __syncthreads();   // all GEMM1 smem reads done before XS overwrite

    #pragma unroll
    for (int j = 0; j < 2; j++) {
        float* gr = XS + (oa0 + j)*XP;
        *(double2*)(gr + tx*4)      = *(double2*)&gd[j][0];
        *(double2*)(gr + 64 + tx*4) = *(double2*)&gd[j][2];
    }
    {
        const float4* wg = (const float4*)(g_w5t + (size_t)b*4096);
        float4* wd = (float4*)WT;
        for (int i = tid; i < 1024; i += 512) wd[i] = wg[i];
    }
    __syncthreads();

    // GEMM2: rows {2ty, 2ty+1}
    double acc2[2][4];
    #pragma unroll
    for (int u = 0; u < 2; u++) { acc2[u][0]=0; acc2[u][1]=0; acc2[u][2]=0; acc2[u][3]=0; }
    #pragma unroll 4
    for (int k = 0; k < 64; k++) {
        float2 w = *(const float2*)(WT + k*64 + oa0);
        double2 xab = *(const double2*)(XS + k*XP + tx*4);
        double2 xcd = *(const double2*)(XS + k*XP + 64 + tx*4);
        double w0 = pack2(w.x, w.x), w1 = pack2(w.y, w.y);
        acc2[0][0] = fma2(w0, xab.x, acc2[0][0]);
        acc2[0][1] = fma2(w0, xab.y, acc2[0][1]);
        acc2[0][2] = fma2(w0, xcd.x, acc2[0][2]);
        acc2[0][3] = fma2(w0, xcd.y, acc2[0][3]);
        acc2[1][0] = fma2(w1, xab.x, acc2[1][0]);
        acc2[1][1] = fma2(w1, xab.y, acc2[1][1]);
        acc2[1][2] = fma2(w1, xcd.x, acc2[1][2]);
        acc2[1][3] = fma2(w1, xcd.y, acc2[1][3]);
    }

    // epilogue: out = y + (acc2 + b5)*gamma (raw y reloaded from gmem)
    float* ob = out + (size_t)b*C*HW + px0;
    #pragma unroll
    for (int u = 0; u < 2; u++) {
        int o = oa0 + u;
        double bp = pack2(B5[o], B5[o]);
        double gp = pack2(GAM[o], GAM[o]);
        double2 y0 = *(const double2*)(ybase + (size_t)o*HW + tx*4);
        double2 y1 = *(const double2*)(ybase + (size_t)o*HW + 64 + tx*4);
        double2 r0, r1;
        r0.x = add2(y0.x, mul2(add2(acc2[u][0], bp), gp));
        r0.y = add2(y0.y, mul2(add2(acc2[u][1], bp), gp));
        r1.x = add2(y1.x, mul2(add2(acc2[u][2], bp), gp));
        r1.y = add2(y1.y, mul2(add2(acc2[u][3], bp), gp));
        *(double2*)(ob + (size_t)o*HW + tx*4)      = r0;
        *(double2*)(ob + (size_t)o*HW + 64 + tx*4) = r1;
    }
}

// ---------------- launch ------------------------------------------------------
extern "C" void kernel_launch(void* const* d_in, const int* in_sizes, int n_in,
                              void* d_out, int out_size) {
    const float* inp   = (const float*)d_in[0];
    const float* w1    = (const float*)d_in[1];
    const float* b1    = (const float*)d_in[2];
    const float* w2    = (const float*)d_in[3];
    const float* b2    = (const float*)d_in[4];
    const float* w3    = (const float*)d_in[5];
    const float* b3    = (const float*)d_in[6];
    const float* w4    = (const float*)d_in[7];
    const float* b4    = (const float*)d_in[8];
    const float* w5    = (const float*)d_in[9];
    const float* b5    = (const float*)d_in[10];
    const float* ln1w  = (const float*)d_in[11];
    const float* ln1b  = (const float*)d_in[12];
    const float* ln2w  = (const float*)d_in[13];
    const float* ln2b  = (const float*)d_in[14];
    const float* scaw  = (const float*)d_in[15];
    const float* scab  = (const float*)d_in[16];
    const float* beta  = (const float*)d_in[17];
    const float* gamma = (const float*)d_in[18];
    float* out = (float*)d_out;

    cudaFuncSetAttribute(k1,  cudaFuncAttributeMaxDynamicSharedMemorySize, 69120);
    cudaFuncSetAttribute(k2a, cudaFuncAttributeMaxDynamicSharedMemorySize, 51200);
    cudaFuncSetAttribute(k2b, cudaFuncAttributeMaxDynamicSharedMemorySize, 69632);

    k_prep<<<4097, 32>>>(w1, w2, w3, w4, w5, ln1w, ln1b, ln2w, ln2b);
    k1 <<<dim3(HW/128, B), 512, 69120>>>(inp, b1);
    kdw<<<dim3(IW/32, IH/32, B*C), 256>>>(b2);
    k2a<<<dim3(HW/128, B), 256, 51200>>>(inp, b3, beta, scaw, scab);
    k2b<<<dim3(HW/128, B), 512, 69632>>>(b4, b5, gamma, out);
}

// round 6
// speedup vs baseline: 1.3815x; 1.0254x over previous
#include <cuda_runtime.h>
#include <math.h>

#define B   8
#define C   64
#define DW  128
#define IH  256
#define IW  256
#define HW  65536
#define EPS 1e-6f
#define XP  132   // smem pitch (floats) for 128-px tiles
#define XP2 264   // smem pitch (floats) for 256-px tiles

// ---------- packed fp32x2 helpers ----------
__device__ __forceinline__ double pack2(float lo, float hi) {
    double r; asm("mov.b64 %0,{%1,%2};" : "=d"(r) : "f"(lo), "f"(hi)); return r;
}
__device__ __forceinline__ double fma2(double a, double b, double c) {
    double r; asm("fma.rn.f32x2 %0,%1,%2,%3;" : "=d"(r) : "d"(a), "d"(b), "d"(c)); return r;
}
__device__ __forceinline__ double add2(double a, double b) {
    double r; asm("add.rn.f32x2 %0,%1,%2;" : "=d"(r) : "d"(a), "d"(b)); return r;
}
__device__ __forceinline__ double mul2(double a, double b) {
    double r; asm("mul.rn.f32x2 %0,%1,%2;" : "=d"(r) : "d"(a), "d"(b)); return r;
}

// ---------------- device scratch ----------------------------------------------
__device__ float g_w1t[B*C*DW];   // k-major, ln1_w-folded
__device__ float g_s1 [B*DW];
__device__ float g_c1 [B*DW];
__device__ float g_w2 [B*DW*9];
__device__ float g_w3t[B*C*C];
__device__ float g_w4t[B*C*DW];   // ln2_w-folded
__device__ float g_s4 [B*DW];
__device__ float g_c4 [B*DW];
__device__ float g_w5t[B*C*C];
__device__ float g_t1[(size_t)B*DW*HW];
__device__ float g_t2[(size_t)B*C*HW];
__device__ float g_pool[B*C];

// ---------------- prep --------------------------------------------------------
__global__ void k_prep(const float* __restrict__ w1, const float* __restrict__ w2,
                       const float* __restrict__ w3, const float* __restrict__ w4,
                       const float* __restrict__ w5,
                       const float* __restrict__ ln1w, const float* __restrict__ ln1b,
                       const float* __restrict__ ln2w, const float* __restrict__ ln2b) {
    int blk = blockIdx.x, t = threadIdx.x;
    if (blk >= 4096) { for (int i = t; i < B*C; i += 32) g_pool[i] = 0.f; return; }

    if (blk < 1024 || (blk >= 2560 && blk < 3584)) {
        bool is1 = (blk < 1024);
        int r = is1 ? blk : blk - 2560;
        const float* src = (is1 ? w1 : w4) + r*64;
        int b = r >> 7, o = r & 127;
        float* dstT = (is1 ? g_w1t : g_w4t) + b*8192 + o;
        const float* lw = is1 ? ln1w : ln2w;
        const float* lb = is1 ? ln1b : ln2b;
        float sq = 0.f;
        for (int i = t; i < 64; i += 32) { float v = src[i]; sq += v*v; }
        #pragma unroll
        for (int off = 16; off; off >>= 1) sq += __shfl_xor_sync(0xffffffffu, sq, off);
        float rn = 1.0f / sqrtf(sq);
        float s = 0.f, cx = 0.f;
        for (int i = t; i < 64; i += 32) {
            float wn = src[i] * rn;
            float wf = wn * lw[i];
            dstT[(size_t)i*128] = wf;
            s += wf; cx += wn * lb[i];
        }
        #pragma unroll
        for (int off = 16; off; off >>= 1) {
            s  += __shfl_xor_sync(0xffffffffu, s,  off);
            cx += __shfl_xor_sync(0xffffffffu, cx, off);
        }
        if (t == 0) {
            if (is1) { g_s1[r] = s; g_c1[r] = cx; }
            else     { g_s4[r] = s; g_c4[r] = cx; }
        }
        return;
    }
    const float* src; float* dstT; int L, stride;
    if (blk < 2048)      { int r = blk - 1024; src=w2+r*9; dstT=g_w2+r*9; stride=1; L=9; }
    else if (blk < 2560) { int r = blk - 2048; int b=r>>6, o=r&63; src=w3+r*64; dstT=g_w3t+b*4096+o; stride=64; L=64; }
    else                 { int r = blk - 3584; int b=r>>6, o=r&63; src=w5+r*64; dstT=g_w5t+b*4096+o; stride=64; L=64; }
    float sq = 0.f;
    for (int i = t; i < L; i += 32) { float v = src[i]; sq += v*v; }
    #pragma unroll
    for (int off = 16; off; off >>= 1) sq += __shfl_xor_sync(0xffffffffu, sq, off);
    float rn = 1.0f / sqrtf(sq);
    for (int i = t; i < L; i += 32) dstT[(size_t)i*stride] = src[i] * rn;
}

// ---------------- K1: LN1(folded) + pw1 GEMM, 8o x 8px per thread -------------
// floats: XS@0(8448) WT@8448(8192) BS@16640(128) SS@16768 CC@16896 MU@17024 RS@17152  tot 17280
__global__ void __launch_bounds__(256, 2) k1(const float* __restrict__ inp,
                                             const float* __restrict__ b1) {
    extern __shared__ float sm[];
    float* XS = sm;          float* WT = sm + 8448;
    float* BS = sm + 16640;  float* SS = sm + 16768; float* CC = sm + 16896;
    float* MU = sm + 17024;  float* RS = sm + 17152;
    int b = blockIdx.y, px0 = blockIdx.x * 128;
    int tid = threadIdx.x, tx = tid & 15, ty = tid >> 4;

    const float* ibase = inp + (size_t)b*C*HW + px0;
    for (int i = tid; i < 2048; i += 256) {
        int c = i >> 5, p4 = i & 31;
        *(float4*)(XS + c*XP + p4*4) = *(const float4*)(ibase + (size_t)c*HW + p4*4);
    }
    {
        const float4* wg = (const float4*)(g_w1t + (size_t)b*8192);
        float4* wd = (float4*)WT;
        for (int i = tid; i < 2048; i += 256) wd[i] = wg[i];
    }
    if (tid < 128) { BS[tid] = b1[b*DW + tid]; SS[tid] = g_s1[b*DW + tid]; CC[tid] = g_c1[b*DW + tid]; }
    __syncthreads();

    if (tid < 128) {
        float s = 0.f, q = 0.f;
        #pragma unroll
        for (int c = 0; c < 64; c++) { float v = XS[c*XP + tid]; s += v; q += v*v; }
        float mu = s * (1.f/64);
        MU[tid] = mu; RS[tid] = rsqrtf(q*(1.f/64) - mu*mu + EPS);
    }
    __syncthreads();

    double acc[8][4];
    #pragma unroll
    for (int u = 0; u < 8; u++) { acc[u][0]=0; acc[u][1]=0; acc[u][2]=0; acc[u][3]=0; }
    int o0 = ty * 8;
    #pragma unroll 4
    for (int k = 0; k < 64; k++) {
        float4 wlo = *(const float4*)(WT + k*128 + o0);
        float4 whi = *(const float4*)(WT + k*128 + o0 + 4);
        double2 xab = *(const double2*)(XS + k*XP + tx*4);
        double2 xcd = *(const double2*)(XS + k*XP + 64 + tx*4);
        double wp[8] = { pack2(wlo.x,wlo.x), pack2(wlo.y,wlo.y), pack2(wlo.z,wlo.z), pack2(wlo.w,wlo.w),
                         pack2(whi.x,whi.x), pack2(whi.y,whi.y), pack2(whi.z,whi.z), pack2(whi.w,whi.w) };
        #pragma unroll
        for (int u = 0; u < 8; u++) {
            acc[u][0] = fma2(wp[u], xab.x, acc[u][0]);
            acc[u][1] = fma2(wp[u], xab.y, acc[u][1]);
            acc[u][2] = fma2(wp[u], xcd.x, acc[u][2]);
            acc[u][3] = fma2(wp[u], xcd.y, acc[u][3]);
        }
    }

    double mu0 = *(const double*)(MU + tx*4), mu1 = *(const double*)(MU + tx*4 + 2);
    double mu2 = *(const double*)(MU + 64 + tx*4), mu3 = *(const double*)(MU + 64 + tx*4 + 2);
    double rs0 = *(const double*)(RS + tx*4), rs1 = *(const double*)(RS + tx*4 + 2);
    double rs2 = *(const double*)(RS + 64 + tx*4), rs3 = *(const double*)(RS + 64 + tx*4 + 2);
    float* op = g_t1 + (size_t)b*DW*HW + px0;
    #pragma unroll
    for (int u = 0; u < 8; u++) {
        int o = o0 + u;
        double nS = pack2(-SS[o], -SS[o]);
        float cbf = CC[o] + BS[o];
        double cb = pack2(cbf, cbf);
        double2 r0, r1;
        r0.x = add2(mul2(fma2(mu0, nS, acc[u][0]), rs0), cb);
        r0.y = add2(mul2(fma2(mu1, nS, acc[u][1]), rs1), cb);
        r1.x = add2(mul2(fma2(mu2, nS, acc[u][2]), rs2), cb);
        r1.y = add2(mul2(fma2(mu3, nS, acc[u][3]), rs3), cb);
        *(double2*)(op + (size_t)o*HW + tx*4)      = r0;
        *(double2*)(op + (size_t)o*HW + 64 + tx*4) = r1;
    }
}

// ---------------- K_dw: depthwise 3x3 + SimpleGate + pool ---------------------
__global__ void __launch_bounds__(256) kdw(const float* __restrict__ b2) {
    int bc = blockIdx.z; int b = bc >> 6; int c = bc & 63;
    __shared__ float s1[34][36];
    __shared__ float s2[34][36];
    __shared__ float wA[9], wB[9], bAB[2], red[8];

    const float* in1 = g_t1 + ((size_t)b*DW + c     ) * HW;
    const float* in2 = g_t1 + ((size_t)b*DW + c + 64) * HW;
    int x0 = blockIdx.x * 32, y0 = blockIdx.y * 32;

    for (int i = threadIdx.x; i < 34*34; i += 256) {
        int ly = i / 34, lx = i % 34;
        int gy = y0 + ly - 1, gx = x0 + lx - 1;
        bool ok = (gy >= 0 && gy < IH && gx >= 0 && gx < IW);
        s1[ly][lx] = ok ? in1[gy*IW + gx] : 0.f;
        s2[ly][lx] = ok ? in2[gy*IW + gx] : 0.f;
    }
    if (threadIdx.x < 9)        wA[threadIdx.x]     = g_w2[((size_t)b*DW + c     )*9 + threadIdx.x];
    else if (threadIdx.x < 18)  wB[threadIdx.x - 9] = g_w2[((size_t)b*DW + c + 64)*9 + threadIdx.x - 9];
    else if (threadIdx.x == 18) bAB[0] = b2[b*DW + c];
    else if (threadIdx.x == 19) bAB[1] = b2[b*DW + c + 64];
    __syncthreads();

    int lx = threadIdx.x & 31, ly0 = (threadIdx.x >> 5) * 4;
    float* obase = g_t2 + ((size_t)b*C + c)*HW;
    float psum = 0.f;
    #pragma unroll
    for (int r = 0; r < 4; r++) {
        int ly = ly0 + r;
        float a = bAB[0], d = bAB[1];
        #pragma unroll
        for (int ky = 0; ky < 3; ky++)
            #pragma unroll
            for (int kx = 0; kx < 3; kx++) {
                a += wA[ky*3 + kx] * s1[ly + ky][lx + kx];
                d += wB[ky*3 + kx] * s2[ly + ky][lx + kx];
            }
        float g = a * d;
        obase[(y0 + ly)*IW + (x0 + lx)] = g;
        psum += g;
    }
    #pragma unroll
    for (int off = 16; off; off >>= 1) psum += __shfl_down_sync(0xffffffffu, psum, off);
    if (lx == 0) red[threadIdx.x >> 5] = psum;
    __syncthreads();
    if (threadIdx.x == 0) {
        float t = 0.f;
        #pragma unroll
        for (int i = 0; i < 8; i++) t += red[i];
        atomicAdd(&g_pool[b*C + c], t);
    }
}

// ---------------- K2a: sca-folded pw3 GEMM, 256-px tile, 8o x 8px -------------
// floats: XS@0(16896=64*264) WT@16896(4096) B3@20992 BET@21056 SCS@21120 PLS@21184  tot 21248
__global__ void __launch_bounds__(256, 2) k2a(const float* __restrict__ inp,
                                              const float* __restrict__ b3,
                                              const float* __restrict__ beta,
                                              const float* __restrict__ sca_w,
                                              const float* __restrict__ sca_b) {
    extern __shared__ float sm[];
    float* XS = sm;          float* WT = sm + 16896;
    float* B3 = sm + 20992;  float* BET = sm + 21056;
    float* SCS = sm + 21120; float* PLS = sm + 21184;
    int b = blockIdx.y, px0 = blockIdx.x * 256;
    int tid = threadIdx.x, tx = tid & 31, ty = tid >> 5;

    const float* t2b = g_t2 + (size_t)b*C*HW + px0;
    for (int i = tid; i < 4096; i += 256) {
        int c = i >> 6, p4 = i & 63;
        *(float4*)(XS + c*XP2 + p4*4) = *(const float4*)(t2b + (size_t)c*HW + p4*4);
    }
    {
        const float4* wg = (const float4*)(g_w3t + (size_t)b*4096);
        float4* wd = (float4*)WT;
        for (int i = tid; i < 1024; i += 256) wd[i] = wg[i];
    }
    if (tid < 64) {
        B3[tid] = b3[b*C + tid]; BET[tid] = beta[tid];
        PLS[tid] = g_pool[b*C + tid] * (1.f/(float)HW);
    }
    __syncthreads();
    if (tid < 64) {
        float acc = sca_b[tid];
        #pragma unroll 8
        for (int cc = 0; cc < 64; cc++) acc += sca_w[tid*64 + cc] * PLS[cc];
        SCS[tid] = acc;
    }
    __syncthreads();
    for (int i = tid; i < 4096; i += 256) WT[i] *= SCS[i >> 6];
    __syncthreads();

    double acc[8][4];
    #pragma unroll
    for (int u = 0; u < 8; u++) { acc[u][0]=0; acc[u][1]=0; acc[u][2]=0; acc[u][3]=0; }
    int o0 = ty * 8;
    #pragma unroll 4
    for (int k = 0; k < 64; k++) {
        float4 wlo = *(const float4*)(WT + k*64 + o0);
        float4 whi = *(const float4*)(WT + k*64 + o0 + 4);
        double2 xab = *(const double2*)(XS + k*XP2 + tx*4);
        double2 xcd = *(const double2*)(XS + k*XP2 + 128 + tx*4);
        double wp[8] = { pack2(wlo.x,wlo.x), pack2(wlo.y,wlo.y), pack2(wlo.z,wlo.z), pack2(wlo.w,wlo.w),
                         pack2(whi.x,whi.x), pack2(whi.y,whi.y), pack2(whi.z,whi.z), pack2(whi.w,whi.w) };
        #pragma unroll
        for (int u = 0; u < 8; u++) {
            acc[u][0] = fma2(wp[u], xab.x, acc[u][0]);
            acc[u][1] = fma2(wp[u], xab.y, acc[u][1]);
            acc[u][2] = fma2(wp[u], xcd.x, acc[u][2]);
            acc[u][3] = fma2(wp[u], xcd.y, acc[u][3]);
        }
    }

    const float* ib = inp + (size_t)b*C*HW + px0;
    float* yb = g_t1 + (size_t)b*C*HW + px0;
    #pragma unroll
    for (int u = 0; u < 8; u++) {
        int o = o0 + u;
        double bp  = pack2(B3[o], B3[o]);
        double btp = pack2(BET[o], BET[o]);
        double2 i0 = *(const double2*)(ib + (size_t)o*HW + tx*4);
        double2 i1 = *(const double2*)(ib + (size_t)o*HW + 128 + tx*4);
        double2 r0, r1;
        r0.x = add2(i0.x, mul2(add2(acc[u][0], bp), btp));
        r0.y = add2(i0.y, mul2(add2(acc[u][1], bp), btp));
        r1.x = add2(i1.x, mul2(add2(acc[u][2], bp), btp));
        r1.y = add2(i1.y, mul2(add2(acc[u][3], bp), btp));
        *(double2*)(yb + (size_t)o*HW + tx*4)       = r0;
        *(double2*)(yb + (size_t)o*HW + 128 + tx*4) = r1;
    }
}

// ---------------- K2b: LN2(folded) -> pw4 -> gate -> pw5 -> out ---------------
// floats: XS@0(8448) WT@8448(8192) B4@16640(128) S4@16768 C4@16896
//         B5@17024(64) GAM@17088(64) MU@17152(128) RS@17280(128)  tot 17408
__global__ void __launch_bounds__(256, 2) k2b(const float* __restrict__ b4,
                                              const float* __restrict__ b5,
                                              const float* __restrict__ gamma,
                                              float* __restrict__ out) {
    extern __shared__ float sm[];
    float* XS = sm;          float* WT = sm + 8448;
    float* B4 = sm + 16640;  float* S4 = sm + 16768; float* C4 = sm + 16896;
    float* B5 = sm + 17024;  float* GAM = sm + 17088;
    float* MU = sm + 17152;  float* RS = sm + 17280;
    int b = blockIdx.y, px0 = blockIdx.x * 128;
    int tid = threadIdx.x, tx = tid & 15, ty = tid >> 4;

    const float* ybase = g_t1 + (size_t)b*C*HW + px0;
    for (int i = tid; i < 2048; i += 256) {
        int c = i >> 5, p4 = i & 31;
        *(float4*)(XS + c*XP + p4*4) = *(const float4*)(ybase + (size_t)c*HW + p4*4);
    }
    {
        const float4* wg = (const float4*)(g_w4t + (size_t)b*8192);
        float4* wd = (float4*)WT;
        for (int i = tid; i < 2048; i += 256) wd[i] = wg[i];
    }
    if (tid < 128) { B4[tid] = b4[b*DW + tid]; S4[tid] = g_s4[b*DW + tid]; C4[tid] = g_c4[b*DW + tid]; }
    else if (tid < 192) { int u = tid - 128; B5[u] = b5[b*C + u]; GAM[u] = gamma[u]; }
    __syncthreads();

    if (tid < 128) {
        float s = 0.f, q = 0.f;
        #pragma unroll
        for (int c = 0; c < 64; c++) { float v = XS[c*XP + tid]; s += v; q += v*v; }
        float mu = s * (1.f/64);
        MU[tid] = mu; RS[tid] = rsqrtf(q*(1.f/64) - mu*mu + EPS);
    }
    __syncthreads();

    // GEMM1 on raw y: rows a = ty*4+{0..3}, rows b = +64
    double acc[8][4];
    #pragma unroll
    for (int u = 0; u < 8; u++) { acc[u][0]=0; acc[u][1]=0; acc[u][2]=0; acc[u][3]=0; }
    int oa0 = ty * 4;
    #pragma unroll 4
    for (int k = 0; k < 64; k++) {
        float4 wlo = *(const float4*)(WT + k*128 + oa0);
        float4 whi = *(const float4*)(WT + k*128 + 64 + oa0);
        double2 xab = *(const double2*)(XS + k*XP + tx*4);
        double2 xcd = *(const double2*)(XS + k*XP + 64 + tx*4);
        double wp[8] = { pack2(wlo.x,wlo.x), pack2(wlo.y,wlo.y), pack2(wlo.z,wlo.z), pack2(wlo.w,wlo.w),
                         pack2(whi.x,whi.x), pack2(whi.y,whi.y), pack2(whi.z,whi.z), pack2(whi.w,whi.w) };
        #pragma unroll
        for (int u = 0; u < 8; u++) {
            acc[u][0] = fma2(wp[u], xab.x, acc[u][0]);
            acc[u][1] = fma2(wp[u], xab.y, acc[u][1]);
            acc[u][2] = fma2(wp[u], xcd.x, acc[u][2]);
            acc[u][3] = fma2(wp[u], xcd.y, acc[u][3]);
        }
    }

    double mu0 = *(const double*)(MU + tx*4), mu1 = *(const double*)(MU + tx*4 + 2);
    double mu2 = *(const double*)(MU + 64 + tx*4), mu3 = *(const double*)(MU + 64 + tx*4 + 2);
    double rs0 = *(const double*)(RS + tx*4), rs1 = *(const double*)(RS + tx*4 + 2);
    double rs2 = *(const double*)(RS + 64 + tx*4), rs3 = *(const double*)(RS + 64 + tx*4 + 2);

    // gate: channels oa0..oa0+3
    double gd[4][4];
    #pragma unroll
    for (int j = 0; j < 4; j++) {
        int oa = oa0 + j, ob = oa + 64;
        double nSa = pack2(-S4[oa], -S4[oa]);
        double nSb = pack2(-S4[ob], -S4[ob]);
        float cbaf = C4[oa] + B4[oa], cbbf = C4[ob] + B4[ob];
        double cba = pack2(cbaf, cbaf), cbb = pack2(cbbf, cbbf);
        double va0 = add2(mul2(fma2(mu0, nSa, acc[j][0]), rs0), cba);
        double va1 = add2(mul2(fma2(mu1, nSa, acc[j][1]), rs1), cba);
        double va2 = add2(mul2(fma2(mu2, nSa, acc[j][2]), rs2), cba);
        double va3 = add2(mul2(fma2(mu3, nSa, acc[j][3]), rs3), cba);
        double vb0 = add2(mul2(fma2(mu0, nSb, acc[j+4][0]), rs0), cbb);
        double vb1 = add2(mul2(fma2(mu1, nSb, acc[j+4][1]), rs1), cbb);
        double vb2 = add2(mul2(fma2(mu2, nSb, acc[j+4][2]), rs2), cbb);
        double vb3 = add2(mul2(fma2(mu3, nSb, acc[j+4][3]), rs3), cbb);
        gd[j][0] = mul2(va0, vb0); gd[j][1] = mul2(va1, vb1);
        gd[j][2] = mul2(va2, vb2); gd[j][3] = mul2(va3, vb3);
    }
    __syncthreads();

    #pragma unroll
    for (int j = 0; j < 4; j++) {
        float* gr = XS + (oa0 + j)*XP;
        *(double2*)(gr + tx*4)      = *(double2*)&gd[j][0];
        *(double2*)(gr + 64 + tx*4) = *(double2*)&gd[j][2];
    }
    {
        const float4* wg = (const float4*)(g_w5t + (size_t)b*4096);
        float4* wd = (float4*)WT;
        for (int i = tid; i < 1024; i += 256) wd[i] = wg[i];
    }
    __syncthreads();

    // GEMM2: 4o x 8px per thread
    double acc2[4][4];
    #pragma unroll
    for (int u = 0; u < 4; u++) { acc2[u][0]=0; acc2[u][1]=0; acc2[u][2]=0; acc2[u][3]=0; }
    #pragma unroll 4
    for (int k = 0; k < 64; k++) {
        float4 w = *(const float4*)(WT + k*64 + oa0);
        double2 xab = *(const double2*)(XS + k*XP + tx*4);
        double2 xcd = *(const double2*)(XS + k*XP + 64 + tx*4);
        double wp[4] = { pack2(w.x,w.x), pack2(w.y,w.y), pack2(w.z,w.z), pack2(w.w,w.w) };
        #pragma unroll
        for (int u = 0; u < 4; u++) {
            acc2[u][0] = fma2(wp[u], xab.x, acc2[u][0]);
            acc2[u][1] = fma2(wp[u], xab.y, acc2[u][1]);
            acc2[u][2] = fma2(wp[u], xcd.x, acc2[u][2]);
            acc2[u][3] = fma2(wp[u], xcd.y, acc2[u][3]);
        }
    }

    float* ob = out + (size_t)b*C*HW + px0;
    #pragma unroll
    for (int u = 0; u < 4; u++) {
        int o = oa0 + u;
        double bp = pack2(B5[o], B5[o]);
        double gp = pack2(GAM[o], GAM[o]);
        double2 y0 = *(const double2*)(ybase + (size_t)o*HW + tx*4);
        double2 y1 = *(const double2*)(ybase + (size_t)o*HW + 64 + tx*4);
        double2 r0, r1;
        r0.x = add2(y0.x, mul2(add2(acc2[u][0], bp), gp));
        r0.y = add2(y0.y, mul2(add2(acc2[u][1], bp), gp));
        r1.x = add2(y1.x, mul2(add2(acc2[u][2], bp), gp));
        r1.y = add2(y1.y, mul2(add2(acc2[u][3], bp), gp));
        *(double2*)(ob + (size_t)o*HW + tx*4)      = r0;
        *(double2*)(ob + (size_t)o*HW + 64 + tx*4) = r1;
    }
}

// ---------------- launch ------------------------------------------------------
extern "C" void kernel_launch(void* const* d_in, const int* in_sizes, int n_in,
                              void* d_out, int out_size) {
    const float* inp   = (const float*)d_in[0];
    const float* w1    = (const float*)d_in[1];
    const float* b1    = (const float*)d_in[2];
    const float* w2    = (const float*)d_in[3];
    const float* b2    = (const float*)d_in[4];
    const float* w3    = (const float*)d_in[5];
    const float* b3    = (const float*)d_in[6];
    const float* w4    = (const float*)d_in[7];
    const float* b4    = (const float*)d_in[8];
    const float* w5    = (const float*)d_in[9];
    const float* b5    = (const float*)d_in[10];
    const float* ln1w  = (const float*)d_in[11];
    const float* ln1b  = (const float*)d_in[12];
    const float* ln2w  = (const float*)d_in[13];
    const float* ln2b  = (const float*)d_in[14];
    const float* scaw  = (const float*)d_in[15];
    const float* scab  = (const float*)d_in[16];
    const float* beta  = (const float*)d_in[17];
    const float* gamma = (const float*)d_in[18];
    float* out = (float*)d_out;

    cudaFuncSetAttribute(k1,  cudaFuncAttributeMaxDynamicSharedMemorySize, 69120);
    cudaFuncSetAttribute(k2a, cudaFuncAttributeMaxDynamicSharedMemorySize, 84992);
    cudaFuncSetAttribute(k2b, cudaFuncAttributeMaxDynamicSharedMemorySize, 69632);

    k_prep<<<4097, 32>>>(w1, w2, w3, w4, w5, ln1w, ln1b, ln2w, ln2b);
    k1 <<<dim3(HW/128, B), 256, 69120>>>(inp, b1);
    kdw<<<dim3(IW/32, IH/32, B*C), 256>>>(b2);
    k2a<<<dim3(HW/256, B), 256, 84992>>>(inp, b3, beta, scaw, scab);
    k2b<<<dim3(HW/128, B), 256, 69632>>>(b4, b5, gamma, out);
}